// round 12
// baseline (speedup 1.0000x reference)
#include <cuda_runtime.h>
#include <cuda_bf16.h>
#include <cstdint>
#include <math.h>

// ---------------- problem constants ----------------
#define BATCH   2
#define LSEQ    2048
#define DM      1024
#define DIP     4384
#define DIPPAD  4480
#define DSSM    2048
#define CONVD   2304
#define NH      32
#define DH      64
#define DS      128
#define CH      128
#define NC      (LSEQ / CH)
#define ROWS    (BATCH * LSEQ)
#define ZOFF    0
#define XBCOFF  2048
#define DTOFF   4352
#define XOFF    0
#define BOFF    2048
#define COFF    2176

// ---------------- scratch ----------------
__device__ float g_zx[ROWS * DIP];
__device__ float g_xc[ROWS * CONVD];
__device__ __nv_bfloat16 g_xcb[ROWS * CONVD];   // bf16 copy of conv output
__device__ float g_dtT[BATCH * NC * NH * CH];
__device__ float g_cumT[BATCH * NC * NH * CH];
__device__ float g_cdecay[BATCH * NC * NH];
__device__ float g_CB[BATCH * NC * CH * CH];
__device__ float g_S[BATCH * NC * NH * DH * DS];
__device__ float g_prev[BATCH * NC * NH * DH * DS];
__device__ float g_y[ROWS * DSSM];

__device__ __nv_bfloat16 g_uhi[ROWS * DM],   g_ulo[ROWS * DM];
__device__ __nv_bfloat16 g_w1hi[DIPPAD * DM], g_w1lo[DIPPAD * DM];
__device__ __nv_bfloat16 g_yhi[ROWS * DSSM], g_ylo[ROWS * DSSM];
__device__ __nv_bfloat16 g_w2hi[DM * DSSM],  g_w2lo[DM * DSSM];

// ---------------- PTX helpers ----------------
__device__ __forceinline__ uint32_t smem_u32(const void* p) {
    return (uint32_t)__cvta_generic_to_shared(p);
}
#define LDMX4(r0,r1,r2,r3,addr) \
    asm volatile("ldmatrix.sync.aligned.m8n8.x4.shared.b16 {%0,%1,%2,%3}, [%4];" \
                 : "=r"(r0),"=r"(r1),"=r"(r2),"=r"(r3) : "r"(addr))
#define LDMX4T(r0,r1,r2,r3,addr) \
    asm volatile("ldmatrix.sync.aligned.m8n8.x4.trans.shared.b16 {%0,%1,%2,%3}, [%4];" \
                 : "=r"(r0),"=r"(r1),"=r"(r2),"=r"(r3) : "r"(addr))
#define MMA16816(d,a,b) \
    asm volatile("mma.sync.aligned.m16n8k16.row.col.f32.bf16.bf16.f32 " \
                 "{%0,%1,%2,%3},{%4,%5,%6,%7},{%8,%9},{%0,%1,%2,%3};" \
                 : "+f"((d)[0]),"+f"((d)[1]),"+f"((d)[2]),"+f"((d)[3]) \
                 : "r"((a)[0]),"r"((a)[1]),"r"((a)[2]),"r"((a)[3]),"r"((b)[0]),"r"((b)[1]))
#define CPASYNC16(s,g) \
    asm volatile("cp.async.cg.shared.global [%0], [%1], 16;" :: "r"(s),"l"(g))
#define CP_COMMIT() asm volatile("cp.async.commit_group;")

// ---------------- fp32 -> bf16 hi/lo split ----------------
__global__ __launch_bounds__(256)
void cvt_split(const float* __restrict__ X, __nv_bfloat16* __restrict__ hi,
               __nv_bfloat16* __restrict__ lo, long nquad, long nquad_src)
{
    long q = (long)blockIdx.x * 256 + threadIdx.x;
    if (q >= nquad) return;
    float4 v = make_float4(0.f, 0.f, 0.f, 0.f);
    if (q < nquad_src) v = *(const float4*)&X[q * 4];
    __nv_bfloat16 h0 = __float2bfloat16(v.x);
    __nv_bfloat16 h1 = __float2bfloat16(v.y);
    __nv_bfloat16 h2 = __float2bfloat16(v.z);
    __nv_bfloat16 h3 = __float2bfloat16(v.w);
    __nv_bfloat16 l0 = __float2bfloat16(v.x - __bfloat162float(h0));
    __nv_bfloat16 l1 = __float2bfloat16(v.y - __bfloat162float(h1));
    __nv_bfloat16 l2 = __float2bfloat16(v.z - __bfloat162float(h2));
    __nv_bfloat16 l3 = __float2bfloat16(v.w - __bfloat162float(h3));
    __nv_bfloat162* hp = (__nv_bfloat162*)&hi[q * 4];
    __nv_bfloat162* lp = (__nv_bfloat162*)&lo[q * 4];
    hp[0] = __nv_bfloat162(h0, h1); hp[1] = __nv_bfloat162(h2, h3);
    lp[0] = __nv_bfloat162(l0, l1); lp[1] = __nv_bfloat162(l2, l3);
}

// ---------------- bf16x3 tensor-core GEMM (128x128, BK=32, persistent, term-major) ----------------
#define SM_STRIDE 40
#define STAGE_ELEMS 20480

__global__ __launch_bounds__(256)
void gemm_bf3(const __nv_bfloat16* __restrict__ Ahi, const __nv_bfloat16* __restrict__ Alo,
              const __nv_bfloat16* __restrict__ Bhi, const __nv_bfloat16* __restrict__ Blo,
              float* __restrict__ C, int M, int N, int K, int ldc,
              int ntx, int ntiles)
{
    extern __shared__ __nv_bfloat16 sm[];
    const uint32_t sbase = smem_u32(sm);
    const int tid = threadIdx.x;
    const int lane = tid & 31, wid = tid >> 5;
    const int wr = wid & 1, wc = wid >> 1;

    const int nt = K >> 5;
    const int ch0 = tid, ch1 = tid + 256;
    const int r0c = ch0 >> 2, s0c = (ch0 & 3) * 8;
    const int r1c = ch1 >> 2, s1c = (ch1 & 3) * 8;

    for (int t = blockIdx.x; t < ntiles; t += gridDim.x) {
        const int row0 = (t / ntx) * 128;
        const int col0 = (t % ntx) * 128;

        float acc[4][4][4];
#pragma unroll
        for (int i = 0; i < 4; i++)
#pragma unroll
            for (int j = 0; j < 4; j++)
#pragma unroll
                for (int k = 0; k < 4; k++) acc[i][j][k] = 0.f;

        auto issue = [&](int kt, int stage) {
            uint32_t sb = sbase + stage * (STAGE_ELEMS * 2);
            CPASYNC16(sb + (r0c * SM_STRIDE + s0c) * 2, Ahi + (long)(row0 + r0c) * K + kt + s0c);
            CPASYNC16(sb + (r1c * SM_STRIDE + s1c) * 2, Ahi + (long)(row0 + r1c) * K + kt + s1c);
            CPASYNC16(sb + (5120 + r0c * SM_STRIDE + s0c) * 2, Alo + (long)(row0 + r0c) * K + kt + s0c);
            CPASYNC16(sb + (5120 + r1c * SM_STRIDE + s1c) * 2, Alo + (long)(row0 + r1c) * K + kt + s1c);
            CPASYNC16(sb + (10240 + r0c * SM_STRIDE + s0c) * 2, Bhi + (long)(col0 + r0c) * K + kt + s0c);
            CPASYNC16(sb + (10240 + r1c * SM_STRIDE + s1c) * 2, Bhi + (long)(col0 + r1c) * K + kt + s1c);
            CPASYNC16(sb + (15360 + r0c * SM_STRIDE + s0c) * 2, Blo + (long)(col0 + r0c) * K + kt + s0c);
            CPASYNC16(sb + (15360 + r1c * SM_STRIDE + s1c) * 2, Blo + (long)(col0 + r1c) * K + kt + s1c);
            CP_COMMIT();
        };

        __syncthreads();     // protect smem against previous tile's readers
        issue(0, 0);

        for (int it = 0; it < nt; it++) {
            asm volatile("cp.async.wait_group 0;");
            __syncthreads();
            if (it + 1 < nt) issue((it + 1) << 5, (it + 1) & 1);

            uint32_t sb = sbase + (it & 1) * (STAGE_ELEMS * 2);
#pragma unroll
            for (int kk = 0; kk < 32; kk += 16) {
                uint32_t ah[4][4], al[4][4], bh[4][2], bl[4][2];
#pragma unroll
                for (int mi = 0; mi < 4; mi++) {
                    int arow = wr * 64 + mi * 16 + (lane & 15);
                    int acol = kk + (lane >> 4) * 8;
                    uint32_t ad = sb + (arow * SM_STRIDE + acol) * 2;
                    LDMX4(ah[mi][0], ah[mi][1], ah[mi][2], ah[mi][3], ad);
                    LDMX4(al[mi][0], al[mi][1], al[mi][2], al[mi][3], ad + 5120 * 2);
                }
#pragma unroll
                for (int half = 0; half < 2; half++) {
                    int brow = wc * 32 + half * 16 + (lane & 7) + ((lane >> 4) & 1) * 8;
                    int bcol = kk + ((lane >> 3) & 1) * 8;
                    uint32_t bd = sb + (10240 + brow * SM_STRIDE + bcol) * 2;
                    uint32_t t0, t1, t2, t3;
                    LDMX4(t0, t1, t2, t3, bd);
                    bh[half*2][0] = t0; bh[half*2][1] = t1;
                    bh[half*2+1][0] = t2; bh[half*2+1][1] = t3;
                    LDMX4(t0, t1, t2, t3, bd + 5120 * 2);
                    bl[half*2][0] = t0; bl[half*2][1] = t1;
                    bl[half*2+1][0] = t2; bl[half*2+1][1] = t3;
                }
                // term-major: 16 independent accumulators between reuses
#pragma unroll
                for (int mi = 0; mi < 4; mi++)
#pragma unroll
                    for (int nj = 0; nj < 4; nj++)
                        MMA16816(acc[mi][nj], ah[mi], bh[nj]);
#pragma unroll
                for (int mi = 0; mi < 4; mi++)
#pragma unroll
                    for (int nj = 0; nj < 4; nj++)
                        MMA16816(acc[mi][nj], ah[mi], bl[nj]);
#pragma unroll
                for (int mi = 0; mi < 4; mi++)
#pragma unroll
                    for (int nj = 0; nj < 4; nj++)
                        MMA16816(acc[mi][nj], al[mi], bh[nj]);
            }
        }

#pragma unroll
        for (int mi = 0; mi < 4; mi++) {
            int r = row0 + wr * 64 + mi * 16 + (lane >> 2);
#pragma unroll
            for (int nj = 0; nj < 4; nj++) {
                int cc = col0 + wc * 32 + nj * 8 + (lane & 3) * 2;
                if (cc < N) {
                    *(float2*)&C[(long)r * ldc + cc] = make_float2(acc[mi][nj][0], acc[mi][nj][1]);
                    *(float2*)&C[(long)(r + 8) * ldc + cc] = make_float2(acc[mi][nj][2], acc[mi][nj][3]);
                }
            }
        }
    }
}

// ---------------- conv1d + silu, emits fp32 + bf16 ----------------
__global__ __launch_bounds__(256)
void conv_silu_kernel(const float* __restrict__ conv_w, const float* __restrict__ conv_b)
{
    __shared__ float t[35][256];
    int tid = threadIdx.x;
    int col = blockIdx.x * 256 + tid;
    int rowstart = blockIdx.y * 32;
    int l0 = rowstart & (LSEQ - 1);

#pragma unroll
    for (int r = 0; r < 35; r++) {
        int l = l0 - 3 + r;
        float v = 0.f;
        if (l >= 0) v = g_zx[(long)(rowstart - 3 + r) * DIP + XBCOFF + col];
        t[r][tid] = v;
    }
    __syncthreads();

    float w0 = conv_w[col * 4 + 0], w1 = conv_w[col * 4 + 1];
    float w2 = conv_w[col * 4 + 2], w3 = conv_w[col * 4 + 3];
    float bb = conv_b[col];
#pragma unroll
    for (int r = 0; r < 32; r++) {
        float acc = bb + t[r][tid] * w0 + t[r + 1][tid] * w1
                       + t[r + 2][tid] * w2 + t[r + 3][tid] * w3;
        float s = acc / (1.f + __expf(-acc));
        g_xc[(long)(rowstart + r) * CONVD + col] = s;
        g_xcb[(long)(rowstart + r) * CONVD + col] = __float2bfloat16(s);
    }
}

// ---------------- dt softplus + per-chunk cumsum ----------------
__global__ __launch_bounds__(256)
void dtcum_kernel(const float* __restrict__ dt_bias, const float* __restrict__ A_log)
{
    __shared__ float sdt[CH][33];
    __shared__ float scum[CH][33];
    int bc = blockIdx.x;
    int b = bc / NC, c = bc % NC;
    int tid = threadIdx.x;
    int rowbase = b * LSEQ + c * CH;

    for (int i = tid; i < CH * NH; i += 256) {
        int l = i >> 5, h = i & 31;
        float raw = g_zx[(long)(rowbase + l) * DIP + DTOFF + h] + dt_bias[h];
        float dtv = (raw > 20.f) ? raw : log1pf(expf(raw));
        sdt[l][h] = dtv;
    }
    __syncthreads();

    if (tid < NH) {
        float Ah = -expf(A_log[tid]);
        float cum = 0.f;
#pragma unroll
        for (int l = 0; l < CH; l++) {
            cum += sdt[l][tid] * Ah;
            scum[l][tid] = cum;
        }
        g_cdecay[bc * NH + tid] = expf(cum);
    }
    __syncthreads();

    for (int i = tid; i < CH * NH; i += 256) {
        int h = i >> 7, l = i & 127;
        g_dtT[(bc * NH + h) * CH + l] = sdt[l][h];
        g_cumT[(bc * NH + h) * CH + l] = scum[l][h];
    }
}

// ---------------- CB = C @ B^T per chunk (bf16 mma) ----------------
__global__ __launch_bounds__(256)
void cb_mma()
{
    extern __shared__ __nv_bfloat16 smc[];
    uint32_t cb = smem_u32(smc);
    uint32_t bb = cb + 17408 * 2;
    int bc = blockIdx.x;
    int b = bc / NC, c = bc % NC;
    int rowbase = b * LSEQ + c * CH;
    int tid = threadIdx.x;
    int lane = tid & 31, wid = tid >> 5;
    int wr = wid & 3, wc = wid >> 2;

    const __nv_bfloat16* Cg = g_xcb + (long)rowbase * CONVD + COFF;
    const __nv_bfloat16* Bg = g_xcb + (long)rowbase * CONVD + BOFF;
#pragma unroll
    for (int k = 0; k < 8; k++) {
        int id = tid + k * 256;
        int s = id >> 4, c8 = (id & 15) * 8;
        CPASYNC16(cb + (s * 136 + c8) * 2, Cg + (long)s * CONVD + c8);
        CPASYNC16(bb + (s * 136 + c8) * 2, Bg + (long)s * CONVD + c8);
    }
    CP_COMMIT();
    asm volatile("cp.async.wait_group 0;");
    __syncthreads();

    float acc[2][8][4];
#pragma unroll
    for (int i = 0; i < 2; i++)
#pragma unroll
        for (int j = 0; j < 8; j++)
#pragma unroll
            for (int k = 0; k < 4; k++) acc[i][j][k] = 0.f;

#pragma unroll
    for (int kk = 0; kk < 128; kk += 16) {
        uint32_t a[2][4];
#pragma unroll
        for (int mi = 0; mi < 2; mi++) {
            int arow = wr * 32 + mi * 16 + (lane & 15);
            int acol = kk + (lane >> 4) * 8;
            LDMX4(a[mi][0], a[mi][1], a[mi][2], a[mi][3], cb + (arow * 136 + acol) * 2);
        }
#pragma unroll
        for (int nb = 0; nb < 4; nb++) {
            int brow = wc * 64 + nb * 16 + (lane & 7) + ((lane >> 4) & 1) * 8;
            int bcol = kk + ((lane >> 3) & 1) * 8;
            uint32_t t0, t1, t2, t3;
            LDMX4(t0, t1, t2, t3, bb + (brow * 136 + bcol) * 2);
            uint32_t b0[2] = {t0, t1}, b1[2] = {t2, t3};
#pragma unroll
            for (int mi = 0; mi < 2; mi++) {
                MMA16816(acc[mi][nb * 2], a[mi], b0);
                MMA16816(acc[mi][nb * 2 + 1], a[mi], b1);
            }
        }
    }

    float* CBo = g_CB + (long)bc * CH * CH;
#pragma unroll
    for (int mi = 0; mi < 2; mi++) {
        int r = wr * 32 + mi * 16 + (lane >> 2);
#pragma unroll
        for (int nj = 0; nj < 8; nj++) {
            int cc = wc * 64 + nj * 8 + (lane & 3) * 2;
            *(float2*)&CBo[r * CH + cc] = make_float2(acc[mi][nj][0], acc[mi][nj][1]);
            *(float2*)&CBo[(r + 8) * CH + cc] = make_float2(acc[mi][nj][2], acc[mi][nj][3]);
        }
    }
}

// ---------------- per-chunk end states (bf16 mma) ----------------
__global__ __launch_bounds__(128)
void states_mma()
{
    extern __shared__ __nv_bfloat16 sms[];
    uint32_t wbase = smem_u32(sms);            // wsx [128][72]
    uint32_t bbase = wbase + 9216 * 2;         // Bb  [128][136]
    __shared__ float ws[CH];

    int bch = blockIdx.x;
    int h = bch % NH;
    int bc = bch / NH;
    int b = bc / NC, c = bc % NC;
    int rowbase = b * LSEQ + c * CH;
    int base = bch * CH;
    int tid = threadIdx.x;
    int lane = tid & 31, wid = tid >> 5;
    int wr = wid & 1, wc = wid >> 1;

    {
        float clast = g_cumT[base + CH - 1];
        ws[tid] = g_dtT[base + tid] * __expf(clast - g_cumT[base + tid]);
    }

    const __nv_bfloat16* Bg = g_xcb + (long)rowbase * CONVD + BOFF;
#pragma unroll
    for (int k = 0; k < 16; k++) {
        int id = tid + k * 128;
        int s = id >> 4, c8 = (id & 15) * 8;
        CPASYNC16(bbase + (s * 136 + c8) * 2, Bg + (long)s * CONVD + c8);
    }
    CP_COMMIT();

    {
        int s = tid;
        float w = ws[s];
        const float* xr = &g_xc[(long)(rowbase + s) * CONVD + XOFF + h * DH];
        __nv_bfloat16* dst = sms + s * 72;
#pragma unroll
        for (int p = 0; p < DH; p += 4) {
            float4 v = *(const float4*)&xr[p];
            __nv_bfloat162* d = (__nv_bfloat162*)&dst[p];
            d[0] = __nv_bfloat162(__float2bfloat16(v.x * w), __float2bfloat16(v.y * w));
            d[1] = __nv_bfloat162(__float2bfloat16(v.z * w), __float2bfloat16(v.w * w));
        }
    }
    asm volatile("cp.async.wait_group 0;");
    __syncthreads();

    float acc[2][8][4];
#pragma unroll
    for (int i = 0; i < 2; i++)
#pragma unroll
        for (int j = 0; j < 8; j++)
#pragma unroll
            for (int k = 0; k < 4; k++) acc[i][j][k] = 0.f;

#pragma unroll
    for (int kk = 0; kk < 128; kk += 16) {
        uint32_t a[2][4];
#pragma unroll
        for (int mi = 0; mi < 2; mi++) {
            int mbase = wr * 32 + mi * 16;
            int srow = kk + (lane & 7) + ((lane >> 4) & 1) * 8;
            int scol = mbase + ((lane >> 3) & 1) * 8;
            LDMX4T(a[mi][0], a[mi][1], a[mi][2], a[mi][3], wbase + (srow * 72 + scol) * 2);
        }
#pragma unroll
        for (int nb = 0; nb < 4; nb++) {
            int nbase = wc * 64 + nb * 16;
            int srow = kk + (lane & 7) + ((lane >> 3) & 1) * 8;
            int scol = nbase + ((lane >> 4) & 1) * 8;
            uint32_t t0, t1, t2, t3;
            LDMX4T(t0, t1, t2, t3, bbase + (srow * 136 + scol) * 2);
            uint32_t b0[2] = {t0, t1}, b1[2] = {t2, t3};
#pragma unroll
            for (int mi = 0; mi < 2; mi++) {
                MMA16816(acc[mi][nb * 2], a[mi], b0);
                MMA16816(acc[mi][nb * 2 + 1], a[mi], b1);
            }
        }
    }

    float* Sp = g_S + (long)bch * DH * DS;
#pragma unroll
    for (int mi = 0; mi < 2; mi++) {
        int r = wr * 32 + mi * 16 + (lane >> 2);
#pragma unroll
        for (int nj = 0; nj < 8; nj++) {
            int cc = wc * 64 + nj * 8 + (lane & 3) * 2;
            *(float2*)&Sp[r * DS + cc] = make_float2(acc[mi][nj][0], acc[mi][nj][1]);
            *(float2*)&Sp[(r + 8) * DS + cc] = make_float2(acc[mi][nj][2], acc[mi][nj][3]);
        }
    }
}

// ---------------- inter-chunk recurrence ----------------
__global__ __launch_bounds__(256)
void scan_kernel()
{
    int bh = blockIdx.x >> 3;
    int slice = blockIdx.x & 7;
    int b = bh >> 5, h = bh & 31;
    int off = slice * 1024 + threadIdx.x * 4;
    float4 carry = make_float4(0.f, 0.f, 0.f, 0.f);
    for (int c = 0; c < NC; c++) {
        int bch = (b * NC + c) * NH + h;
        float d = g_cdecay[bch];
        long idx = (long)bch * (DH * DS) + off;
        float4 s = *(const float4*)&g_S[idx];
        *(float4*)&g_prev[idx] = carry;
        carry.x = carry.x * d + s.x;
        carry.y = carry.y * d + s.y;
        carry.z = carry.z * d + s.z;
        carry.w = carry.w * d + s.w;
    }
}

// ---------------- Y = intra + inter + D*x (bf16 mma) ----------------
__global__ __launch_bounds__(128)
void y_mma(const float* __restrict__ Dparam)
{
    extern __shared__ __nv_bfloat16 smy[];
    uint32_t xb = smem_u32(smy);               // phase1: xb [128][72]
    uint32_t ms = xb + 9216 * 2;               // phase1: Ms [128][24]
    uint32_t ec = xb;                          // phase2: ElC [128][136]
    uint32_t pb = xb + 17408 * 2;              // phase2: prevb [64][136]
    __shared__ float cl[CH], dts[CH], Fg[CH], El[CH];

    int bch = blockIdx.x;
    int h = bch % NH;
    int bc = bch / NH;
    int b = bc / NC, c = bc % NC;
    int rowbase = b * LSEQ + c * CH;
    int base = bch * CH;
    int tid = threadIdx.x;
    int lane = tid & 31, wid = tid >> 5;

    {
        float cv = g_cumT[base + tid];
        cl[tid] = cv;
        dts[tid] = g_dtT[base + tid];
        El[tid] = __expf(cv);
    }
    const __nv_bfloat16* xg = g_xcb + (long)rowbase * CONVD + XOFF + h * DH;
#pragma unroll
    for (int k = 0; k < 8; k++) {
        int id = tid + k * 128;
        int s = id >> 3, c8 = (id & 7) * 8;
        CPASYNC16(xb + (s * 72 + c8) * 2, xg + (long)s * CONVD + c8);
    }
    CP_COMMIT();
    __syncthreads();
    Fg[tid] = __expf(cl[tid] - cl[tid & ~7]);
    asm volatile("cp.async.wait_group 0;");
    __syncthreads();

    float acc[2][8][4];
#pragma unroll
    for (int i = 0; i < 2; i++)
#pragma unroll
        for (int j = 0; j < 8; j++)
#pragma unroll
            for (int k = 0; k < 4; k++) acc[i][j][k] = 0.f;

    const float* CBp = g_CB + (long)bc * CH * CH;

    // ---- phase 1: Y_intra ----
    for (int kt = 0; kt < 128; kt += 16) {
        {
            int sg = kt + (tid & 15);
            int l0 = (tid >> 4) * 16;
            float dsg = dts[sg], csg = cl[sg];
            int scc = sg - kt;
#pragma unroll
            for (int g = 0; g < 2; g++) {
                int lb = l0 + g * 8;
                float e0 = __expf(fminf(cl[lb] - csg, 85.f)) * dsg;
#pragma unroll
                for (int i = 0; i < 8; i++) {
                    int lg = lb + i;
                    float v = (sg <= lg) ? CBp[lg * CH + sg] * Fg[lg] * e0 : 0.f;
                    smy[9216 + lg * 24 + scc] = __float2bfloat16(v);
                }
            }
        }
        __syncthreads();
        if (kt <= wid * 32 + 31) {
            uint32_t a[2][4];
#pragma unroll
            for (int mi = 0; mi < 2; mi++) {
                int arow = wid * 32 + mi * 16 + (lane & 15);
                int acol = (lane >> 4) * 8;
                LDMX4(a[mi][0], a[mi][1], a[mi][2], a[mi][3], ms + (arow * 24 + acol) * 2);
            }
#pragma unroll
            for (int nb = 0; nb < 4; nb++) {
                int nbase = nb * 16;
                int srow = kt + (lane & 7) + ((lane >> 3) & 1) * 8;
                int scol = nbase + ((lane >> 4) & 1) * 8;
                uint32_t t0, t1, t2, t3;
                LDMX4T(t0, t1, t2, t3, xb + (srow * 72 + scol) * 2);
                uint32_t b0[2] = {t0, t1}, b1[2] = {t2, t3};
#pragma unroll
                for (int mi = 0; mi < 2; mi++) {
                    MMA16816(acc[mi][nb * 2], a[mi], b0);
                    MMA16816(acc[mi][nb * 2 + 1], a[mi], b1);
                }
            }
        }
        __syncthreads();
    }

    // ---- phase 2 staging ----
    {
        int l = tid;
        float el = El[l];
        const __nv_bfloat16* Cg = g_xcb + (long)(rowbase + l) * CONVD + COFF;
        __nv_bfloat16* dst = smy + l * 136;
#pragma unroll
        for (int n = 0; n < 128; n += 2) {
            __nv_bfloat162 cv = *(const __nv_bfloat162*)&Cg[n];
            *(__nv_bfloat162*)&dst[n] = __nv_bfloat162(
                __float2bfloat16(__bfloat162float(cv.x) * el),
                __float2bfloat16(__bfloat162float(cv.y) * el));
        }
        const float* Pv = g_prev + (long)bch * DH * DS;
        int p = tid >> 1, n0 = (tid & 1) * 64;
        __nv_bfloat16* pdst = smy + 17408 + p * 136;
#pragma unroll
        for (int n = 0; n < 64; n += 4) {
            float4 v = *(const float4*)&Pv[p * DS + n0 + n];
            __nv_bfloat162* d = (__nv_bfloat162*)&pdst[n0 + n];
            d[0] = __nv_bfloat162(__float2bfloat16(v.x), __float2bfloat16(v.y));
            d[1] = __nv_bfloat162(__float2bfloat16(v.z), __float2bfloat16(v.w));
        }
    }
    __syncthreads();

    // ---- phase 2: Y_inter ----
#pragma unroll
    for (int nt = 0; nt < 128; nt += 16) {
        uint32_t a[2][4];
#pragma unroll
        for (int mi = 0; mi < 2; mi++) {
            int arow = wid * 32 + mi * 16 + (lane & 15);
            int acol = nt + (lane >> 4) * 8;
            LDMX4(a[mi][0], a[mi][1], a[mi][2], a[mi][3], ec + (arow * 136 + acol) * 2);
        }
#pragma unroll
        for (int nb = 0; nb < 4; nb++) {
            int brow = nb * 16 + (lane & 7) + ((lane >> 4) & 1) * 8;
            int bcol = nt + ((lane >> 3) & 1) * 8;
            uint32_t t0, t1, t2, t3;
            LDMX4(t0, t1, t2, t3, pb + (brow * 136 + bcol) * 2);
            uint32_t b0[2] = {t0, t1}, b1[2] = {t2, t3};
#pragma unroll
            for (int mi = 0; mi < 2; mi++) {
                MMA16816(acc[mi][nb * 2], a[mi], b0);
                MMA16816(acc[mi][nb * 2 + 1], a[mi], b1);
            }
        }
    }

    // ---- epilogue ----
    float Dh = Dparam[h];
#pragma unroll
    for (int mi = 0; mi < 2; mi++) {
        int r = wid * 32 + mi * 16 + (lane >> 2);
#pragma unroll
        for (int nj = 0; nj < 8; nj++) {
            int cc = nj * 8 + (lane & 3) * 2;
            {
                int row = rowbase + r;
                float2 xv = *(const float2*)&g_xc[(long)row * CONVD + XOFF + h * DH + cc];
                *(float2*)&g_y[(long)row * DSSM + h * DH + cc] =
                    make_float2(acc[mi][nj][0] + Dh * xv.x, acc[mi][nj][1] + Dh * xv.y);
            }
            {
                int row = rowbase + r + 8;
                float2 xv = *(const float2*)&g_xc[(long)row * CONVD + XOFF + h * DH + cc];
                *(float2*)&g_y[(long)row * DSSM + h * DH + cc] =
                    make_float2(acc[mi][nj][2] + Dh * xv.x, acc[mi][nj][3] + Dh * xv.y);
            }
        }
    }
}

// ---------------- gate + RMSNorm, emits bf16 hi/lo ----------------
__global__ __launch_bounds__(256)
void gatenorm_kernel(const float* __restrict__ norm_w)
{
    int row = blockIdx.x;
    int tid = threadIdx.x;
    float v[8];
    float ss = 0.f;
#pragma unroll
    for (int j = 0; j < 8; j++) {
        int cidx = tid + j * 256;
        float y = g_y[(long)row * DSSM + cidx];
        float z = g_zx[(long)row * DIP + ZOFF + cidx];
        float g = z / (1.f + __expf(-z));
        float yg = y * g;
        v[j] = yg;
        ss += yg * yg;
    }
#pragma unroll
    for (int o = 16; o > 0; o >>= 1) ss += __shfl_xor_sync(0xffffffffu, ss, o);
    __shared__ float red[8];
    __shared__ float rinv;
    if ((tid & 31) == 0) red[tid >> 5] = ss;
    __syncthreads();
    if (tid == 0) {
        float t = 0.f;
#pragma unroll
        for (int i = 0; i < 8; i++) t += red[i];
        rinv = rsqrtf(t / (float)DSSM + 1e-5f);
    }
    __syncthreads();
    float r = rinv;
#pragma unroll
    for (int j = 0; j < 8; j++) {
        int cidx = tid + j * 256;
        float val = v[j] * r * norm_w[cidx];
        __nv_bfloat16 hh = __float2bfloat16(val);
        __nv_bfloat16 ll = __float2bfloat16(val - __bfloat162float(hh));
        g_yhi[(long)row * DSSM + cidx] = hh;
        g_ylo[(long)row * DSSM + cidx] = ll;
    }
}

// ---------------- host launcher ----------------
extern "C" void kernel_launch(void* const* d_in, const int* in_sizes, int n_in,
                              void* d_out, int out_size)
{
    const float* u       = (const float*)d_in[0];
    const float* W_in    = (const float*)d_in[1];
    const float* conv_w  = (const float*)d_in[2];
    const float* conv_b  = (const float*)d_in[3];
    const float* dt_bias = (const float*)d_in[4];
    const float* A_log   = (const float*)d_in[5];
    const float* Dp      = (const float*)d_in[6];
    const float* norm_w  = (const float*)d_in[7];
    const float* W_out   = (const float*)d_in[8];
    float* out = (float*)d_out;

    float *p_zx;
    cudaGetSymbolAddress((void**)&p_zx, g_zx);
    __nv_bfloat16 *p_uhi, *p_ulo, *p_w1hi, *p_w1lo, *p_yhi, *p_ylo, *p_w2hi, *p_w2lo;
    cudaGetSymbolAddress((void**)&p_uhi, g_uhi);
    cudaGetSymbolAddress((void**)&p_ulo, g_ulo);
    cudaGetSymbolAddress((void**)&p_w1hi, g_w1hi);
    cudaGetSymbolAddress((void**)&p_w1lo, g_w1lo);
    cudaGetSymbolAddress((void**)&p_yhi, g_yhi);
    cudaGetSymbolAddress((void**)&p_ylo, g_ylo);
    cudaGetSymbolAddress((void**)&p_w2hi, g_w2hi);
    cudaGetSymbolAddress((void**)&p_w2lo, g_w2lo);

    static int smem_set = 0;
    if (!smem_set) {
        cudaFuncSetAttribute(gemm_bf3, cudaFuncAttributeMaxDynamicSharedMemorySize, 2 * STAGE_ELEMS * 2);
        cudaFuncSetAttribute(cb_mma, cudaFuncAttributeMaxDynamicSharedMemorySize, 69632);
        cudaFuncSetAttribute(states_mma, cudaFuncAttributeMaxDynamicSharedMemorySize, 53248);
        cudaFuncSetAttribute(y_mma, cudaFuncAttributeMaxDynamicSharedMemorySize, 52224);
        smem_set = 1;
    }

    // 0) bf16 hi/lo conversions
    {
        long nq = (long)ROWS * DM / 4;
        cvt_split<<<(nq + 255) / 256, 256>>>(u, p_uhi, p_ulo, nq, nq);
    }
    {
        long nq = (long)DIPPAD * DM / 4, ns = (long)DIP * DM / 4;
        cvt_split<<<(nq + 255) / 256, 256>>>(W_in, p_w1hi, p_w1lo, nq, ns);
    }
    {
        long nq = (long)DM * DSSM / 4;
        cvt_split<<<(nq + 255) / 256, 256>>>(W_out, p_w2hi, p_w2lo, nq, nq);
    }

    // 1) in_proj (persistent: 296 CTAs over 1120 tiles)
    gemm_bf3<<<296, 256, 2 * STAGE_ELEMS * 2>>>(
        p_uhi, p_ulo, p_w1hi, p_w1lo, p_zx, ROWS, DIP, DM, DIP,
        DIPPAD / 128, (DIPPAD / 128) * (ROWS / 128));

    // 2) conv + silu
    conv_silu_kernel<<<dim3(CONVD / 256, ROWS / 32), 256>>>(conv_w, conv_b);

    // 3) dt / cumsum
    dtcum_kernel<<<BATCH * NC, 256>>>(dt_bias, A_log);

    // 4) CB
    cb_mma<<<BATCH * NC, 256, 69632>>>();

    // 5) states
    states_mma<<<BATCH * NC * NH, 128, 53248>>>();

    // 6) scan
    scan_kernel<<<BATCH * NH * 8, 256>>>();

    // 7) Y
    y_mma<<<BATCH * NC * NH, 128, 52224>>>(Dp);

    // 8) gate + RMSNorm
    gatenorm_kernel<<<ROWS, 256>>>(norm_w);

    // 9) out_proj (256 tiles, single wave)
    gemm_bf3<<<256, 256, 2 * STAGE_ELEMS * 2>>>(
        p_yhi, p_ylo, p_w2hi, p_w2lo, out, ROWS, DM, DSSM, DM,
        DM / 128, (DM / 128) * (ROWS / 128));

    (void)in_sizes; (void)n_in; (void)out_size;
}

// round 13
// speedup vs baseline: 1.1119x; 1.1119x over previous
#include <cuda_runtime.h>
#include <cuda_bf16.h>
#include <cstdint>
#include <math.h>

// ---------------- problem constants ----------------
#define BATCH   2
#define LSEQ    2048
#define DM      1024
#define DIP     4384
#define DIPPAD  4480
#define DSSM    2048
#define CONVD   2304
#define NH      32
#define DH      64
#define DS      128
#define CH      128
#define NC      (LSEQ / CH)
#define ROWS    (BATCH * LSEQ)
#define ZOFF    0
#define XBCOFF  2048
#define DTOFF   4352
#define XOFF    0
#define BOFF    2048
#define COFF    2176

// ---------------- scratch ----------------
__device__ float g_zx[ROWS * DIP];
__device__ float g_xc[ROWS * CONVD];
__device__ __nv_bfloat16 g_xcb[ROWS * CONVD];   // bf16 copy of conv output
__device__ float g_dtT[BATCH * NC * NH * CH];
__device__ float g_cumT[BATCH * NC * NH * CH];
__device__ float g_cdecay[BATCH * NC * NH];
__device__ float g_CB[BATCH * NC * CH * CH];
__device__ float g_S[BATCH * NC * NH * DH * DS];
__device__ float g_prev[BATCH * NC * NH * DH * DS];
__device__ float g_y[ROWS * DSSM];

__device__ __nv_bfloat16 g_uhi[ROWS * DM],   g_ulo[ROWS * DM];
__device__ __nv_bfloat16 g_w1hi[DIPPAD * DM], g_w1lo[DIPPAD * DM];
__device__ __nv_bfloat16 g_yhi[ROWS * DSSM], g_ylo[ROWS * DSSM];
__device__ __nv_bfloat16 g_w2hi[DM * DSSM],  g_w2lo[DM * DSSM];

// ---------------- PTX helpers ----------------
__device__ __forceinline__ uint32_t smem_u32(const void* p) {
    return (uint32_t)__cvta_generic_to_shared(p);
}
#define LDMX4(r0,r1,r2,r3,addr) \
    asm volatile("ldmatrix.sync.aligned.m8n8.x4.shared.b16 {%0,%1,%2,%3}, [%4];" \
                 : "=r"(r0),"=r"(r1),"=r"(r2),"=r"(r3) : "r"(addr))
#define LDMX4T(r0,r1,r2,r3,addr) \
    asm volatile("ldmatrix.sync.aligned.m8n8.x4.trans.shared.b16 {%0,%1,%2,%3}, [%4];" \
                 : "=r"(r0),"=r"(r1),"=r"(r2),"=r"(r3) : "r"(addr))
#define MMA16816(d,a,b) \
    asm volatile("mma.sync.aligned.m16n8k16.row.col.f32.bf16.bf16.f32 " \
                 "{%0,%1,%2,%3},{%4,%5,%6,%7},{%8,%9},{%0,%1,%2,%3};" \
                 : "+f"((d)[0]),"+f"((d)[1]),"+f"((d)[2]),"+f"((d)[3]) \
                 : "r"((a)[0]),"r"((a)[1]),"r"((a)[2]),"r"((a)[3]),"r"((b)[0]),"r"((b)[1]))
#define CPASYNC16(s,g) \
    asm volatile("cp.async.cg.shared.global [%0], [%1], 16;" :: "r"(s),"l"(g))
#define CP_COMMIT() asm volatile("cp.async.commit_group;")

// ---------------- fp32 -> bf16 hi/lo split ----------------
__global__ __launch_bounds__(256)
void cvt_split(const float* __restrict__ X, __nv_bfloat16* __restrict__ hi,
               __nv_bfloat16* __restrict__ lo, long nquad, long nquad_src)
{
    long q = (long)blockIdx.x * 256 + threadIdx.x;
    if (q >= nquad) return;
    float4 v = make_float4(0.f, 0.f, 0.f, 0.f);
    if (q < nquad_src) v = *(const float4*)&X[q * 4];
    __nv_bfloat16 h0 = __float2bfloat16(v.x);
    __nv_bfloat16 h1 = __float2bfloat16(v.y);
    __nv_bfloat16 h2 = __float2bfloat16(v.z);
    __nv_bfloat16 h3 = __float2bfloat16(v.w);
    __nv_bfloat16 l0 = __float2bfloat16(v.x - __bfloat162float(h0));
    __nv_bfloat16 l1 = __float2bfloat16(v.y - __bfloat162float(h1));
    __nv_bfloat16 l2 = __float2bfloat16(v.z - __bfloat162float(h2));
    __nv_bfloat16 l3 = __float2bfloat16(v.w - __bfloat162float(h3));
    __nv_bfloat162* hp = (__nv_bfloat162*)&hi[q * 4];
    __nv_bfloat162* lp = (__nv_bfloat162*)&lo[q * 4];
    hp[0] = __nv_bfloat162(h0, h1); hp[1] = __nv_bfloat162(h2, h3);
    lp[0] = __nv_bfloat162(l0, l1); lp[1] = __nv_bfloat162(l2, l3);
}

// ---------------- bf16x3 tensor-core GEMM (128x128, BK=32, 2-stage, term-major MMAs) ----------------
#define SM_STRIDE 40
#define STAGE_ELEMS 20480

__global__ __launch_bounds__(256)
void gemm_bf3(const __nv_bfloat16* __restrict__ Ahi, const __nv_bfloat16* __restrict__ Alo,
              const __nv_bfloat16* __restrict__ Bhi, const __nv_bfloat16* __restrict__ Blo,
              float* __restrict__ C, int M, int N, int K, int ldc)
{
    extern __shared__ __nv_bfloat16 sm[];
    const uint32_t sbase = smem_u32(sm);
    const int tid = threadIdx.x;
    const int lane = tid & 31, wid = tid >> 5;
    const int wr = wid & 1, wc = wid >> 1;
    const int row0 = blockIdx.y * 128;
    const int col0 = blockIdx.x * 128;

    float acc[4][4][4];
#pragma unroll
    for (int i = 0; i < 4; i++)
#pragma unroll
        for (int j = 0; j < 4; j++)
#pragma unroll
            for (int k = 0; k < 4; k++) acc[i][j][k] = 0.f;

    const int nt = K >> 5;
    const int ch0 = tid, ch1 = tid + 256;
    const int r0c = ch0 >> 2, s0c = (ch0 & 3) * 8;
    const int r1c = ch1 >> 2, s1c = (ch1 & 3) * 8;

    auto issue = [&](int kt, int stage) {
        uint32_t sb = sbase + stage * (STAGE_ELEMS * 2);
        CPASYNC16(sb + (r0c * SM_STRIDE + s0c) * 2, Ahi + (long)(row0 + r0c) * K + kt + s0c);
        CPASYNC16(sb + (r1c * SM_STRIDE + s1c) * 2, Ahi + (long)(row0 + r1c) * K + kt + s1c);
        CPASYNC16(sb + (5120 + r0c * SM_STRIDE + s0c) * 2, Alo + (long)(row0 + r0c) * K + kt + s0c);
        CPASYNC16(sb + (5120 + r1c * SM_STRIDE + s1c) * 2, Alo + (long)(row0 + r1c) * K + kt + s1c);
        CPASYNC16(sb + (10240 + r0c * SM_STRIDE + s0c) * 2, Bhi + (long)(col0 + r0c) * K + kt + s0c);
        CPASYNC16(sb + (10240 + r1c * SM_STRIDE + s1c) * 2, Bhi + (long)(col0 + r1c) * K + kt + s1c);
        CPASYNC16(sb + (15360 + r0c * SM_STRIDE + s0c) * 2, Blo + (long)(col0 + r0c) * K + kt + s0c);
        CPASYNC16(sb + (15360 + r1c * SM_STRIDE + s1c) * 2, Blo + (long)(col0 + r1c) * K + kt + s1c);
        CP_COMMIT();
    };

    issue(0, 0);

    for (int it = 0; it < nt; it++) {
        asm volatile("cp.async.wait_group 0;");
        __syncthreads();
        if (it + 1 < nt) issue((it + 1) << 5, (it + 1) & 1);

        uint32_t sb = sbase + (it & 1) * (STAGE_ELEMS * 2);
#pragma unroll
        for (int kk = 0; kk < 32; kk += 16) {
            uint32_t ah[4][4], al[4][4], bh[4][2], bl[4][2];
#pragma unroll
            for (int mi = 0; mi < 4; mi++) {
                int arow = wr * 64 + mi * 16 + (lane & 15);
                int acol = kk + (lane >> 4) * 8;
                uint32_t ad = sb + (arow * SM_STRIDE + acol) * 2;
                LDMX4(ah[mi][0], ah[mi][1], ah[mi][2], ah[mi][3], ad);
                LDMX4(al[mi][0], al[mi][1], al[mi][2], al[mi][3], ad + 5120 * 2);
            }
#pragma unroll
            for (int half = 0; half < 2; half++) {
                int brow = wc * 32 + half * 16 + (lane & 7) + ((lane >> 4) & 1) * 8;
                int bcol = kk + ((lane >> 3) & 1) * 8;
                uint32_t bd = sb + (10240 + brow * SM_STRIDE + bcol) * 2;
                uint32_t t0, t1, t2, t3;
                LDMX4(t0, t1, t2, t3, bd);
                bh[half*2][0] = t0; bh[half*2][1] = t1;
                bh[half*2+1][0] = t2; bh[half*2+1][1] = t3;
                LDMX4(t0, t1, t2, t3, bd + 5120 * 2);
                bl[half*2][0] = t0; bl[half*2][1] = t1;
                bl[half*2+1][0] = t2; bl[half*2+1][1] = t3;
            }
            // term-major: 16 independent accumulators between any reuse
#pragma unroll
            for (int mi = 0; mi < 4; mi++)
#pragma unroll
                for (int nj = 0; nj < 4; nj++)
                    MMA16816(acc[mi][nj], ah[mi], bh[nj]);
#pragma unroll
            for (int mi = 0; mi < 4; mi++)
#pragma unroll
                for (int nj = 0; nj < 4; nj++)
                    MMA16816(acc[mi][nj], ah[mi], bl[nj]);
#pragma unroll
            for (int mi = 0; mi < 4; mi++)
#pragma unroll
                for (int nj = 0; nj < 4; nj++)
                    MMA16816(acc[mi][nj], al[mi], bh[nj]);
        }
    }

#pragma unroll
    for (int mi = 0; mi < 4; mi++) {
        int r = row0 + wr * 64 + mi * 16 + (lane >> 2);
#pragma unroll
        for (int nj = 0; nj < 4; nj++) {
            int cc = col0 + wc * 32 + nj * 8 + (lane & 3) * 2;
            if (cc < N) {
                *(float2*)&C[(long)r * ldc + cc] = make_float2(acc[mi][nj][0], acc[mi][nj][1]);
                *(float2*)&C[(long)(r + 8) * ldc + cc] = make_float2(acc[mi][nj][2], acc[mi][nj][3]);
            }
        }
    }
}

// ---------------- conv1d + silu, emits fp32 + bf16 ----------------
__global__ __launch_bounds__(256)
void conv_silu_kernel(const float* __restrict__ conv_w, const float* __restrict__ conv_b)
{
    __shared__ float t[35][256];
    int tid = threadIdx.x;
    int col = blockIdx.x * 256 + tid;
    int rowstart = blockIdx.y * 32;
    int l0 = rowstart & (LSEQ - 1);

#pragma unroll
    for (int r = 0; r < 35; r++) {
        int l = l0 - 3 + r;
        float v = 0.f;
        if (l >= 0) v = g_zx[(long)(rowstart - 3 + r) * DIP + XBCOFF + col];
        t[r][tid] = v;
    }
    __syncthreads();

    float w0 = conv_w[col * 4 + 0], w1 = conv_w[col * 4 + 1];
    float w2 = conv_w[col * 4 + 2], w3 = conv_w[col * 4 + 3];
    float bb = conv_b[col];
#pragma unroll
    for (int r = 0; r < 32; r++) {
        float acc = bb + t[r][tid] * w0 + t[r + 1][tid] * w1
                       + t[r + 2][tid] * w2 + t[r + 3][tid] * w3;
        float s = acc / (1.f + __expf(-acc));
        g_xc[(long)(rowstart + r) * CONVD + col] = s;
        g_xcb[(long)(rowstart + r) * CONVD + col] = __float2bfloat16(s);
    }
}

// ---------------- dt softplus + per-chunk cumsum ----------------
__global__ __launch_bounds__(256)
void dtcum_kernel(const float* __restrict__ dt_bias, const float* __restrict__ A_log)
{
    __shared__ float sdt[CH][33];
    __shared__ float scum[CH][33];
    int bc = blockIdx.x;
    int b = bc / NC, c = bc % NC;
    int tid = threadIdx.x;
    int rowbase = b * LSEQ + c * CH;

    for (int i = tid; i < CH * NH; i += 256) {
        int l = i >> 5, h = i & 31;
        float raw = g_zx[(long)(rowbase + l) * DIP + DTOFF + h] + dt_bias[h];
        float dtv = (raw > 20.f) ? raw : log1pf(expf(raw));
        sdt[l][h] = dtv;
    }
    __syncthreads();

    if (tid < NH) {
        float Ah = -expf(A_log[tid]);
        float cum = 0.f;
#pragma unroll
        for (int l = 0; l < CH; l++) {
            cum += sdt[l][tid] * Ah;
            scum[l][tid] = cum;
        }
        g_cdecay[bc * NH + tid] = expf(cum);
    }
    __syncthreads();

    for (int i = tid; i < CH * NH; i += 256) {
        int h = i >> 7, l = i & 127;
        g_dtT[(bc * NH + h) * CH + l] = sdt[l][h];
        g_cumT[(bc * NH + h) * CH + l] = scum[l][h];
    }
}

// ---------------- CB = C @ B^T per chunk (bf16 mma) ----------------
__global__ __launch_bounds__(256)
void cb_mma()
{
    extern __shared__ __nv_bfloat16 smc[];
    uint32_t cb = smem_u32(smc);
    uint32_t bb = cb + 17408 * 2;
    int bc = blockIdx.x;
    int b = bc / NC, c = bc % NC;
    int rowbase = b * LSEQ + c * CH;
    int tid = threadIdx.x;
    int lane = tid & 31, wid = tid >> 5;
    int wr = wid & 3, wc = wid >> 2;

    const __nv_bfloat16* Cg = g_xcb + (long)rowbase * CONVD + COFF;
    const __nv_bfloat16* Bg = g_xcb + (long)rowbase * CONVD + BOFF;
#pragma unroll
    for (int k = 0; k < 8; k++) {
        int id = tid + k * 256;
        int s = id >> 4, c8 = (id & 15) * 8;
        CPASYNC16(cb + (s * 136 + c8) * 2, Cg + (long)s * CONVD + c8);
        CPASYNC16(bb + (s * 136 + c8) * 2, Bg + (long)s * CONVD + c8);
    }
    CP_COMMIT();
    asm volatile("cp.async.wait_group 0;");
    __syncthreads();

    float acc[2][8][4];
#pragma unroll
    for (int i = 0; i < 2; i++)
#pragma unroll
        for (int j = 0; j < 8; j++)
#pragma unroll
            for (int k = 0; k < 4; k++) acc[i][j][k] = 0.f;

#pragma unroll
    for (int kk = 0; kk < 128; kk += 16) {
        uint32_t a[2][4];
#pragma unroll
        for (int mi = 0; mi < 2; mi++) {
            int arow = wr * 32 + mi * 16 + (lane & 15);
            int acol = kk + (lane >> 4) * 8;
            LDMX4(a[mi][0], a[mi][1], a[mi][2], a[mi][3], cb + (arow * 136 + acol) * 2);
        }
#pragma unroll
        for (int nb = 0; nb < 4; nb++) {
            int brow = wc * 64 + nb * 16 + (lane & 7) + ((lane >> 4) & 1) * 8;
            int bcol = kk + ((lane >> 3) & 1) * 8;
            uint32_t t0, t1, t2, t3;
            LDMX4(t0, t1, t2, t3, bb + (brow * 136 + bcol) * 2);
            uint32_t b0[2] = {t0, t1}, b1[2] = {t2, t3};
#pragma unroll
            for (int mi = 0; mi < 2; mi++) {
                MMA16816(acc[mi][nb * 2], a[mi], b0);
                MMA16816(acc[mi][nb * 2 + 1], a[mi], b1);
            }
        }
    }

    float* CBo = g_CB + (long)bc * CH * CH;
#pragma unroll
    for (int mi = 0; mi < 2; mi++) {
        int r = wr * 32 + mi * 16 + (lane >> 2);
#pragma unroll
        for (int nj = 0; nj < 8; nj++) {
            int cc = wc * 64 + nj * 8 + (lane & 3) * 2;
            *(float2*)&CBo[r * CH + cc] = make_float2(acc[mi][nj][0], acc[mi][nj][1]);
            *(float2*)&CBo[(r + 8) * CH + cc] = make_float2(acc[mi][nj][2], acc[mi][nj][3]);
        }
    }
}

// ---------------- per-chunk end states (bf16 mma) ----------------
__global__ __launch_bounds__(128)
void states_mma()
{
    extern __shared__ __nv_bfloat16 sms[];
    uint32_t wbase = smem_u32(sms);            // wsx [128][72]
    uint32_t bbase = wbase + 9216 * 2;         // Bb  [128][136]
    __shared__ float ws[CH];

    int bch = blockIdx.x;
    int h = bch % NH;
    int bc = bch / NH;
    int b = bc / NC, c = bc % NC;
    int rowbase = b * LSEQ + c * CH;
    int base = bch * CH;
    int tid = threadIdx.x;
    int lane = tid & 31, wid = tid >> 5;
    int wr = wid & 1, wc = wid >> 1;

    {
        float clast = g_cumT[base + CH - 1];
        ws[tid] = g_dtT[base + tid] * __expf(clast - g_cumT[base + tid]);
    }

    const __nv_bfloat16* Bg = g_xcb + (long)rowbase * CONVD + BOFF;
#pragma unroll
    for (int k = 0; k < 16; k++) {
        int id = tid + k * 128;
        int s = id >> 4, c8 = (id & 15) * 8;
        CPASYNC16(bbase + (s * 136 + c8) * 2, Bg + (long)s * CONVD + c8);
    }
    CP_COMMIT();

    {
        int s = tid;
        float w = ws[s];
        const float* xr = &g_xc[(long)(rowbase + s) * CONVD + XOFF + h * DH];
        __nv_bfloat16* dst = sms + s * 72;
#pragma unroll
        for (int p = 0; p < DH; p += 4) {
            float4 v = *(const float4*)&xr[p];
            __nv_bfloat162* d = (__nv_bfloat162*)&dst[p];
            d[0] = __nv_bfloat162(__float2bfloat16(v.x * w), __float2bfloat16(v.y * w));
            d[1] = __nv_bfloat162(__float2bfloat16(v.z * w), __float2bfloat16(v.w * w));
        }
    }
    asm volatile("cp.async.wait_group 0;");
    __syncthreads();

    float acc[2][8][4];
#pragma unroll
    for (int i = 0; i < 2; i++)
#pragma unroll
        for (int j = 0; j < 8; j++)
#pragma unroll
            for (int k = 0; k < 4; k++) acc[i][j][k] = 0.f;

#pragma unroll
    for (int kk = 0; kk < 128; kk += 16) {
        uint32_t a[2][4];
#pragma unroll
        for (int mi = 0; mi < 2; mi++) {
            int mbase = wr * 32 + mi * 16;
            int srow = kk + (lane & 7) + ((lane >> 4) & 1) * 8;
            int scol = mbase + ((lane >> 3) & 1) * 8;
            LDMX4T(a[mi][0], a[mi][1], a[mi][2], a[mi][3], wbase + (srow * 72 + scol) * 2);
        }
#pragma unroll
        for (int nb = 0; nb < 4; nb++) {
            int nbase = wc * 64 + nb * 16;
            int srow = kk + (lane & 7) + ((lane >> 3) & 1) * 8;
            int scol = nbase + ((lane >> 4) & 1) * 8;
            uint32_t t0, t1, t2, t3;
            LDMX4T(t0, t1, t2, t3, bbase + (srow * 136 + scol) * 2);
            uint32_t b0[2] = {t0, t1}, b1[2] = {t2, t3};
#pragma unroll
            for (int mi = 0; mi < 2; mi++) {
                MMA16816(acc[mi][nb * 2], a[mi], b0);
                MMA16816(acc[mi][nb * 2 + 1], a[mi], b1);
            }
        }
    }

    float* Sp = g_S + (long)bch * DH * DS;
#pragma unroll
    for (int mi = 0; mi < 2; mi++) {
        int r = wr * 32 + mi * 16 + (lane >> 2);
#pragma unroll
        for (int nj = 0; nj < 8; nj++) {
            int cc = wc * 64 + nj * 8 + (lane & 3) * 2;
            *(float2*)&Sp[r * DS + cc] = make_float2(acc[mi][nj][0], acc[mi][nj][1]);
            *(float2*)&Sp[(r + 8) * DS + cc] = make_float2(acc[mi][nj][2], acc[mi][nj][3]);
        }
    }
}

// ---------------- inter-chunk recurrence ----------------
__global__ __launch_bounds__(256)
void scan_kernel()
{
    int bh = blockIdx.x >> 3;
    int slice = blockIdx.x & 7;
    int b = bh >> 5, h = bh & 31;
    int off = slice * 1024 + threadIdx.x * 4;
    float4 carry = make_float4(0.f, 0.f, 0.f, 0.f);
    for (int c = 0; c < NC; c++) {
        int bch = (b * NC + c) * NH + h;
        float d = g_cdecay[bch];
        long idx = (long)bch * (DH * DS) + off;
        float4 s = *(const float4*)&g_S[idx];
        *(float4*)&g_prev[idx] = carry;
        carry.x = carry.x * d + s.x;
        carry.y = carry.y * d + s.y;
        carry.z = carry.z * d + s.z;
        carry.w = carry.w * d + s.w;
    }
}

// ---------------- Y = intra + inter + D*x (bf16 mma) ----------------
__global__ __launch_bounds__(128)
void y_mma(const float* __restrict__ Dparam)
{
    extern __shared__ __nv_bfloat16 smy[];
    uint32_t xb = smem_u32(smy);               // phase1: xb [128][72]
    uint32_t ms = xb + 9216 * 2;               // phase1: Ms [128][24]
    uint32_t ec = xb;                          // phase2: ElC [128][136]
    uint32_t pb = xb + 17408 * 2;              // phase2: prevb [64][136]
    __shared__ float cl[CH], dts[CH], Fg[CH], El[CH];

    int bch = blockIdx.x;
    int h = bch % NH;
    int bc = bch / NH;
    int b = bc / NC, c = bc % NC;
    int rowbase = b * LSEQ + c * CH;
    int base = bch * CH;
    int tid = threadIdx.x;
    int lane = tid & 31, wid = tid >> 5;

    {
        float cv = g_cumT[base + tid];
        cl[tid] = cv;
        dts[tid] = g_dtT[base + tid];
        El[tid] = __expf(cv);
    }
    const __nv_bfloat16* xg = g_xcb + (long)rowbase * CONVD + XOFF + h * DH;
#pragma unroll
    for (int k = 0; k < 8; k++) {
        int id = tid + k * 128;
        int s = id >> 3, c8 = (id & 7) * 8;
        CPASYNC16(xb + (s * 72 + c8) * 2, xg + (long)s * CONVD + c8);
    }
    CP_COMMIT();
    __syncthreads();
    Fg[tid] = __expf(cl[tid] - cl[tid & ~7]);
    asm volatile("cp.async.wait_group 0;");
    __syncthreads();

    float acc[2][8][4];
#pragma unroll
    for (int i = 0; i < 2; i++)
#pragma unroll
        for (int j = 0; j < 8; j++)
#pragma unroll
            for (int k = 0; k < 4; k++) acc[i][j][k] = 0.f;

    const float* CBp = g_CB + (long)bc * CH * CH;

    // ---- phase 1: Y_intra ----
    for (int kt = 0; kt < 128; kt += 16) {
        {
            int sg = kt + (tid & 15);
            int l0 = (tid >> 4) * 16;
            float dsg = dts[sg], csg = cl[sg];
            int scc = sg - kt;
#pragma unroll
            for (int g = 0; g < 2; g++) {
                int lb = l0 + g * 8;
                float e0 = __expf(fminf(cl[lb] - csg, 85.f)) * dsg;
#pragma unroll
                for (int i = 0; i < 8; i++) {
                    int lg = lb + i;
                    float v = (sg <= lg) ? CBp[lg * CH + sg] * Fg[lg] * e0 : 0.f;
                    smy[9216 + lg * 24 + scc] = __float2bfloat16(v);
                }
            }
        }
        __syncthreads();
        if (kt <= wid * 32 + 31) {
            uint32_t a[2][4];
#pragma unroll
            for (int mi = 0; mi < 2; mi++) {
                int arow = wid * 32 + mi * 16 + (lane & 15);
                int acol = (lane >> 4) * 8;
                LDMX4(a[mi][0], a[mi][1], a[mi][2], a[mi][3], ms + (arow * 24 + acol) * 2);
            }
#pragma unroll
            for (int nb = 0; nb < 4; nb++) {
                int nbase = nb * 16;
                int srow = kt + (lane & 7) + ((lane >> 3) & 1) * 8;
                int scol = nbase + ((lane >> 4) & 1) * 8;
                uint32_t t0, t1, t2, t3;
                LDMX4T(t0, t1, t2, t3, xb + (srow * 72 + scol) * 2);
                uint32_t b0[2] = {t0, t1}, b1[2] = {t2, t3};
#pragma unroll
                for (int mi = 0; mi < 2; mi++) {
                    MMA16816(acc[mi][nb * 2], a[mi], b0);
                    MMA16816(acc[mi][nb * 2 + 1], a[mi], b1);
                }
            }
        }
        __syncthreads();
    }

    // ---- phase 2 staging ----
    {
        int l = tid;
        float el = El[l];
        const __nv_bfloat16* Cg = g_xcb + (long)(rowbase + l) * CONVD + COFF;
        __nv_bfloat16* dst = smy + l * 136;
#pragma unroll
        for (int n = 0; n < 128; n += 2) {
            __nv_bfloat162 cv = *(const __nv_bfloat162*)&Cg[n];
            *(__nv_bfloat162*)&dst[n] = __nv_bfloat162(
                __float2bfloat16(__bfloat162float(cv.x) * el),
                __float2bfloat16(__bfloat162float(cv.y) * el));
        }
        const float* Pv = g_prev + (long)bch * DH * DS;
        int p = tid >> 1, n0 = (tid & 1) * 64;
        __nv_bfloat16* pdst = smy + 17408 + p * 136;
#pragma unroll
        for (int n = 0; n < 64; n += 4) {
            float4 v = *(const float4*)&Pv[p * DS + n0 + n];
            __nv_bfloat162* d = (__nv_bfloat162*)&pdst[n0 + n];
            d[0] = __nv_bfloat162(__float2bfloat16(v.x), __float2bfloat16(v.y));
            d[1] = __nv_bfloat162(__float2bfloat16(v.z), __float2bfloat16(v.w));
        }
    }
    __syncthreads();

    // ---- phase 2: Y_inter ----
#pragma unroll
    for (int nt = 0; nt < 128; nt += 16) {
        uint32_t a[2][4];
#pragma unroll
        for (int mi = 0; mi < 2; mi++) {
            int arow = wid * 32 + mi * 16 + (lane & 15);
            int acol = nt + (lane >> 4) * 8;
            LDMX4(a[mi][0], a[mi][1], a[mi][2], a[mi][3], ec + (arow * 136 + acol) * 2);
        }
#pragma unroll
        for (int nb = 0; nb < 4; nb++) {
            int brow = nb * 16 + (lane & 7) + ((lane >> 4) & 1) * 8;
            int bcol = nt + ((lane >> 3) & 1) * 8;
            uint32_t t0, t1, t2, t3;
            LDMX4(t0, t1, t2, t3, pb + (brow * 136 + bcol) * 2);
            uint32_t b0[2] = {t0, t1}, b1[2] = {t2, t3};
#pragma unroll
            for (int mi = 0; mi < 2; mi++) {
                MMA16816(acc[mi][nb * 2], a[mi], b0);
                MMA16816(acc[mi][nb * 2 + 1], a[mi], b1);
            }
        }
    }

    // ---- epilogue ----
    float Dh = Dparam[h];
#pragma unroll
    for (int mi = 0; mi < 2; mi++) {
        int r = wid * 32 + mi * 16 + (lane >> 2);
#pragma unroll
        for (int nj = 0; nj < 8; nj++) {
            int cc = nj * 8 + (lane & 3) * 2;
            {
                int row = rowbase + r;
                float2 xv = *(const float2*)&g_xc[(long)row * CONVD + XOFF + h * DH + cc];
                *(float2*)&g_y[(long)row * DSSM + h * DH + cc] =
                    make_float2(acc[mi][nj][0] + Dh * xv.x, acc[mi][nj][1] + Dh * xv.y);
            }
            {
                int row = rowbase + r + 8;
                float2 xv = *(const float2*)&g_xc[(long)row * CONVD + XOFF + h * DH + cc];
                *(float2*)&g_y[(long)row * DSSM + h * DH + cc] =
                    make_float2(acc[mi][nj][2] + Dh * xv.x, acc[mi][nj][3] + Dh * xv.y);
            }
        }
    }
}

// ---------------- gate + RMSNorm, emits bf16 hi/lo ----------------
__global__ __launch_bounds__(256)
void gatenorm_kernel(const float* __restrict__ norm_w)
{
    int row = blockIdx.x;
    int tid = threadIdx.x;
    float v[8];
    float ss = 0.f;
#pragma unroll
    for (int j = 0; j < 8; j++) {
        int cidx = tid + j * 256;
        float y = g_y[(long)row * DSSM + cidx];
        float z = g_zx[(long)row * DIP + ZOFF + cidx];
        float g = z / (1.f + __expf(-z));
        float yg = y * g;
        v[j] = yg;
        ss += yg * yg;
    }
#pragma unroll
    for (int o = 16; o > 0; o >>= 1) ss += __shfl_xor_sync(0xffffffffu, ss, o);
    __shared__ float red[8];
    __shared__ float rinv;
    if ((tid & 31) == 0) red[tid >> 5] = ss;
    __syncthreads();
    if (tid == 0) {
        float t = 0.f;
#pragma unroll
        for (int i = 0; i < 8; i++) t += red[i];
        rinv = rsqrtf(t / (float)DSSM + 1e-5f);
    }
    __syncthreads();
    float r = rinv;
#pragma unroll
    for (int j = 0; j < 8; j++) {
        int cidx = tid + j * 256;
        float val = v[j] * r * norm_w[cidx];
        __nv_bfloat16 hh = __float2bfloat16(val);
        __nv_bfloat16 ll = __float2bfloat16(val - __bfloat162float(hh));
        g_yhi[(long)row * DSSM + cidx] = hh;
        g_ylo[(long)row * DSSM + cidx] = ll;
    }
}

// ---------------- host launcher ----------------
extern "C" void kernel_launch(void* const* d_in, const int* in_sizes, int n_in,
                              void* d_out, int out_size)
{
    const float* u       = (const float*)d_in[0];
    const float* W_in    = (const float*)d_in[1];
    const float* conv_w  = (const float*)d_in[2];
    const float* conv_b  = (const float*)d_in[3];
    const float* dt_bias = (const float*)d_in[4];
    const float* A_log   = (const float*)d_in[5];
    const float* Dp      = (const float*)d_in[6];
    const float* norm_w  = (const float*)d_in[7];
    const float* W_out   = (const float*)d_in[8];
    float* out = (float*)d_out;

    float *p_zx;
    cudaGetSymbolAddress((void**)&p_zx, g_zx);
    __nv_bfloat16 *p_uhi, *p_ulo, *p_w1hi, *p_w1lo, *p_yhi, *p_ylo, *p_w2hi, *p_w2lo;
    cudaGetSymbolAddress((void**)&p_uhi, g_uhi);
    cudaGetSymbolAddress((void**)&p_ulo, g_ulo);
    cudaGetSymbolAddress((void**)&p_w1hi, g_w1hi);
    cudaGetSymbolAddress((void**)&p_w1lo, g_w1lo);
    cudaGetSymbolAddress((void**)&p_yhi, g_yhi);
    cudaGetSymbolAddress((void**)&p_ylo, g_ylo);
    cudaGetSymbolAddress((void**)&p_w2hi, g_w2hi);
    cudaGetSymbolAddress((void**)&p_w2lo, g_w2lo);

    static int smem_set = 0;
    if (!smem_set) {
        cudaFuncSetAttribute(gemm_bf3, cudaFuncAttributeMaxDynamicSharedMemorySize, 2 * STAGE_ELEMS * 2);
        cudaFuncSetAttribute(cb_mma, cudaFuncAttributeMaxDynamicSharedMemorySize, 69632);
        cudaFuncSetAttribute(states_mma, cudaFuncAttributeMaxDynamicSharedMemorySize, 53248);
        cudaFuncSetAttribute(y_mma, cudaFuncAttributeMaxDynamicSharedMemorySize, 52224);
        smem_set = 1;
    }

    // 0) bf16 hi/lo conversions
    {
        long nq = (long)ROWS * DM / 4;
        cvt_split<<<(nq + 255) / 256, 256>>>(u, p_uhi, p_ulo, nq, nq);
    }
    {
        long nq = (long)DIPPAD * DM / 4, ns = (long)DIP * DM / 4;
        cvt_split<<<(nq + 255) / 256, 256>>>(W_in, p_w1hi, p_w1lo, nq, ns);
    }
    {
        long nq = (long)DM * DSSM / 4;
        cvt_split<<<(nq + 255) / 256, 256>>>(W_out, p_w2hi, p_w2lo, nq, nq);
    }

    // 1) in_proj
    gemm_bf3<<<dim3(DIPPAD / 128, ROWS / 128), 256, 2 * STAGE_ELEMS * 2>>>(
        p_uhi, p_ulo, p_w1hi, p_w1lo, p_zx, ROWS, DIP, DM, DIP);

    // 2) conv + silu
    conv_silu_kernel<<<dim3(CONVD / 256, ROWS / 32), 256>>>(conv_w, conv_b);

    // 3) dt / cumsum
    dtcum_kernel<<<BATCH * NC, 256>>>(dt_bias, A_log);

    // 4) CB
    cb_mma<<<BATCH * NC, 256, 69632>>>();

    // 5) states
    states_mma<<<BATCH * NC * NH, 128, 53248>>>();

    // 6) scan
    scan_kernel<<<BATCH * NH * 8, 256>>>();

    // 7) Y
    y_mma<<<BATCH * NC * NH, 128, 52224>>>(Dp);

    // 8) gate + RMSNorm
    gatenorm_kernel<<<ROWS, 256>>>(norm_w);

    // 9) out_proj
    gemm_bf3<<<dim3(DM / 128, ROWS / 128), 256, 2 * STAGE_ELEMS * 2>>>(
        p_yhi, p_ylo, p_w2hi, p_w2lo, out, ROWS, DM, DSSM, DM);

    (void)in_sizes; (void)n_in; (void)out_size;
}

// round 14
// speedup vs baseline: 1.1406x; 1.0258x over previous
#include <cuda_runtime.h>
#include <cuda_bf16.h>
#include <cstdint>
#include <math.h>

// ---------------- problem constants ----------------
#define BATCH   2
#define LSEQ    2048
#define DM      1024
#define DIP     4384
#define DIPPAD  4480
#define DSSM    2048
#define CONVD   2304
#define NH      32
#define DH      64
#define DS      128
#define CH      128
#define NC      (LSEQ / CH)
#define ROWS    (BATCH * LSEQ)
#define ZOFF    0
#define XBCOFF  2048
#define DTOFF   4352
#define XOFF    0
#define BOFF    2048
#define COFF    2176

// ---------------- scratch ----------------
__device__ float g_zx[ROWS * DIP];
__device__ float g_xc[ROWS * CONVD];
__device__ __nv_bfloat16 g_xcb[ROWS * CONVD];   // bf16 copy of conv output
__device__ float g_dtT[BATCH * NC * NH * CH];
__device__ float g_cumT[BATCH * NC * NH * CH];
__device__ float g_cdecay[BATCH * NC * NH];
__device__ float g_CB[BATCH * NC * CH * CH];
__device__ float g_S[BATCH * NC * NH * DH * DS];
__device__ float g_prev[BATCH * NC * NH * DH * DS];
__device__ float g_y[ROWS * DSSM];

__device__ __nv_bfloat16 g_uhi[ROWS * DM],   g_ulo[ROWS * DM];
__device__ __nv_bfloat16 g_w1hi[DIPPAD * DM], g_w1lo[DIPPAD * DM];
__device__ __nv_bfloat16 g_yhi[ROWS * DSSM], g_ylo[ROWS * DSSM];
__device__ __nv_bfloat16 g_w2hi[DM * DSSM],  g_w2lo[DM * DSSM];

// ---------------- PTX helpers ----------------
__device__ __forceinline__ uint32_t smem_u32(const void* p) {
    return (uint32_t)__cvta_generic_to_shared(p);
}
#define LDMX4(r0,r1,r2,r3,addr) \
    asm volatile("ldmatrix.sync.aligned.m8n8.x4.shared.b16 {%0,%1,%2,%3}, [%4];" \
                 : "=r"(r0),"=r"(r1),"=r"(r2),"=r"(r3) : "r"(addr))
#define LDMX4T(r0,r1,r2,r3,addr) \
    asm volatile("ldmatrix.sync.aligned.m8n8.x4.trans.shared.b16 {%0,%1,%2,%3}, [%4];" \
                 : "=r"(r0),"=r"(r1),"=r"(r2),"=r"(r3) : "r"(addr))
#define MMA16816(d,a,b) \
    asm volatile("mma.sync.aligned.m16n8k16.row.col.f32.bf16.bf16.f32 " \
                 "{%0,%1,%2,%3},{%4,%5,%6,%7},{%8,%9},{%0,%1,%2,%3};" \
                 : "+f"((d)[0]),"+f"((d)[1]),"+f"((d)[2]),"+f"((d)[3]) \
                 : "r"((a)[0]),"r"((a)[1]),"r"((a)[2]),"r"((a)[3]),"r"((b)[0]),"r"((b)[1]))
#define CPASYNC16(s,g) \
    asm volatile("cp.async.cg.shared.global [%0], [%1], 16;" :: "r"(s),"l"(g))
#define CP_COMMIT() asm volatile("cp.async.commit_group;")

// ---------------- fp32 -> bf16 hi/lo split ----------------
__global__ __launch_bounds__(256)
void cvt_split(const float* __restrict__ X, __nv_bfloat16* __restrict__ hi,
               __nv_bfloat16* __restrict__ lo, long nquad, long nquad_src)
{
    long q = (long)blockIdx.x * 256 + threadIdx.x;
    if (q >= nquad) return;
    float4 v = make_float4(0.f, 0.f, 0.f, 0.f);
    if (q < nquad_src) v = *(const float4*)&X[q * 4];
    __nv_bfloat16 h0 = __float2bfloat16(v.x);
    __nv_bfloat16 h1 = __float2bfloat16(v.y);
    __nv_bfloat16 h2 = __float2bfloat16(v.z);
    __nv_bfloat16 h3 = __float2bfloat16(v.w);
    __nv_bfloat16 l0 = __float2bfloat16(v.x - __bfloat162float(h0));
    __nv_bfloat16 l1 = __float2bfloat16(v.y - __bfloat162float(h1));
    __nv_bfloat16 l2 = __float2bfloat16(v.z - __bfloat162float(h2));
    __nv_bfloat16 l3 = __float2bfloat16(v.w - __bfloat162float(h3));
    __nv_bfloat162* hp = (__nv_bfloat162*)&hi[q * 4];
    __nv_bfloat162* lp = (__nv_bfloat162*)&lo[q * 4];
    hp[0] = __nv_bfloat162(h0, h1); hp[1] = __nv_bfloat162(h2, h3);
    lp[0] = __nv_bfloat162(l0, l1); lp[1] = __nv_bfloat162(l2, l3);
}

// ---------------- bf16x3 tensor-core GEMM (unchanged from best) ----------------
#define SM_STRIDE 40
#define STAGE_ELEMS 20480

__global__ __launch_bounds__(256)
void gemm_bf3(const __nv_bfloat16* __restrict__ Ahi, const __nv_bfloat16* __restrict__ Alo,
              const __nv_bfloat16* __restrict__ Bhi, const __nv_bfloat16* __restrict__ Blo,
              float* __restrict__ C, int M, int N, int K, int ldc)
{
    extern __shared__ __nv_bfloat16 sm[];
    const uint32_t sbase = smem_u32(sm);
    const int tid = threadIdx.x;
    const int lane = tid & 31, wid = tid >> 5;
    const int wr = wid & 1, wc = wid >> 1;
    const int row0 = blockIdx.y * 128;
    const int col0 = blockIdx.x * 128;

    float acc[4][4][4];
#pragma unroll
    for (int i = 0; i < 4; i++)
#pragma unroll
        for (int j = 0; j < 4; j++)
#pragma unroll
            for (int k = 0; k < 4; k++) acc[i][j][k] = 0.f;

    const int nt = K >> 5;
    const int ch0 = tid, ch1 = tid + 256;
    const int r0c = ch0 >> 2, s0c = (ch0 & 3) * 8;
    const int r1c = ch1 >> 2, s1c = (ch1 & 3) * 8;

    auto issue = [&](int kt, int stage) {
        uint32_t sb = sbase + stage * (STAGE_ELEMS * 2);
        CPASYNC16(sb + (r0c * SM_STRIDE + s0c) * 2, Ahi + (long)(row0 + r0c) * K + kt + s0c);
        CPASYNC16(sb + (r1c * SM_STRIDE + s1c) * 2, Ahi + (long)(row0 + r1c) * K + kt + s1c);
        CPASYNC16(sb + (5120 + r0c * SM_STRIDE + s0c) * 2, Alo + (long)(row0 + r0c) * K + kt + s0c);
        CPASYNC16(sb + (5120 + r1c * SM_STRIDE + s1c) * 2, Alo + (long)(row0 + r1c) * K + kt + s1c);
        CPASYNC16(sb + (10240 + r0c * SM_STRIDE + s0c) * 2, Bhi + (long)(col0 + r0c) * K + kt + s0c);
        CPASYNC16(sb + (10240 + r1c * SM_STRIDE + s1c) * 2, Bhi + (long)(col0 + r1c) * K + kt + s1c);
        CPASYNC16(sb + (15360 + r0c * SM_STRIDE + s0c) * 2, Blo + (long)(col0 + r0c) * K + kt + s0c);
        CPASYNC16(sb + (15360 + r1c * SM_STRIDE + s1c) * 2, Blo + (long)(col0 + r1c) * K + kt + s1c);
        CP_COMMIT();
    };

    issue(0, 0);

    for (int it = 0; it < nt; it++) {
        asm volatile("cp.async.wait_group 0;");
        __syncthreads();
        if (it + 1 < nt) issue((it + 1) << 5, (it + 1) & 1);

        uint32_t sb = sbase + (it & 1) * (STAGE_ELEMS * 2);
#pragma unroll
        for (int kk = 0; kk < 32; kk += 16) {
            uint32_t ah[4][4], al[4][4], bh[4][2], bl[4][2];
#pragma unroll
            for (int mi = 0; mi < 4; mi++) {
                int arow = wr * 64 + mi * 16 + (lane & 15);
                int acol = kk + (lane >> 4) * 8;
                uint32_t ad = sb + (arow * SM_STRIDE + acol) * 2;
                LDMX4(ah[mi][0], ah[mi][1], ah[mi][2], ah[mi][3], ad);
                LDMX4(al[mi][0], al[mi][1], al[mi][2], al[mi][3], ad + 5120 * 2);
            }
#pragma unroll
            for (int half = 0; half < 2; half++) {
                int brow = wc * 32 + half * 16 + (lane & 7) + ((lane >> 4) & 1) * 8;
                int bcol = kk + ((lane >> 3) & 1) * 8;
                uint32_t bd = sb + (10240 + brow * SM_STRIDE + bcol) * 2;
                uint32_t t0, t1, t2, t3;
                LDMX4(t0, t1, t2, t3, bd);
                bh[half*2][0] = t0; bh[half*2][1] = t1;
                bh[half*2+1][0] = t2; bh[half*2+1][1] = t3;
                LDMX4(t0, t1, t2, t3, bd + 5120 * 2);
                bl[half*2][0] = t0; bl[half*2][1] = t1;
                bl[half*2+1][0] = t2; bl[half*2+1][1] = t3;
            }
#pragma unroll
            for (int mi = 0; mi < 4; mi++)
#pragma unroll
                for (int nj = 0; nj < 4; nj++)
                    MMA16816(acc[mi][nj], ah[mi], bh[nj]);
#pragma unroll
            for (int mi = 0; mi < 4; mi++)
#pragma unroll
                for (int nj = 0; nj < 4; nj++)
                    MMA16816(acc[mi][nj], ah[mi], bl[nj]);
#pragma unroll
            for (int mi = 0; mi < 4; mi++)
#pragma unroll
                for (int nj = 0; nj < 4; nj++)
                    MMA16816(acc[mi][nj], al[mi], bh[nj]);
        }
    }

#pragma unroll
    for (int mi = 0; mi < 4; mi++) {
        int r = row0 + wr * 64 + mi * 16 + (lane >> 2);
#pragma unroll
        for (int nj = 0; nj < 4; nj++) {
            int cc = col0 + wc * 32 + nj * 8 + (lane & 3) * 2;
            if (cc < N) {
                *(float2*)&C[(long)r * ldc + cc] = make_float2(acc[mi][nj][0], acc[mi][nj][1]);
                *(float2*)&C[(long)(r + 8) * ldc + cc] = make_float2(acc[mi][nj][2], acc[mi][nj][3]);
            }
        }
    }
}

// ---------------- conv1d + silu, emits fp32 + bf16 ----------------
__global__ __launch_bounds__(256)
void conv_silu_kernel(const float* __restrict__ conv_w, const float* __restrict__ conv_b)
{
    __shared__ float t[35][256];
    int tid = threadIdx.x;
    int col = blockIdx.x * 256 + tid;
    int rowstart = blockIdx.y * 32;
    int l0 = rowstart & (LSEQ - 1);

#pragma unroll
    for (int r = 0; r < 35; r++) {
        int l = l0 - 3 + r;
        float v = 0.f;
        if (l >= 0) v = g_zx[(long)(rowstart - 3 + r) * DIP + XBCOFF + col];
        t[r][tid] = v;
    }
    __syncthreads();

    float w0 = conv_w[col * 4 + 0], w1 = conv_w[col * 4 + 1];
    float w2 = conv_w[col * 4 + 2], w3 = conv_w[col * 4 + 3];
    float bb = conv_b[col];
#pragma unroll
    for (int r = 0; r < 32; r++) {
        float acc = bb + t[r][tid] * w0 + t[r + 1][tid] * w1
                       + t[r + 2][tid] * w2 + t[r + 3][tid] * w3;
        float s = acc / (1.f + __expf(-acc));
        g_xc[(long)(rowstart + r) * CONVD + col] = s;
        g_xcb[(long)(rowstart + r) * CONVD + col] = __float2bfloat16(s);
    }
}

// ---------------- dt softplus + per-chunk cumsum ----------------
__global__ __launch_bounds__(256)
void dtcum_kernel(const float* __restrict__ dt_bias, const float* __restrict__ A_log)
{
    __shared__ float sdt[CH][33];
    __shared__ float scum[CH][33];
    int bc = blockIdx.x;
    int b = bc / NC, c = bc % NC;
    int tid = threadIdx.x;
    int rowbase = b * LSEQ + c * CH;

    for (int i = tid; i < CH * NH; i += 256) {
        int l = i >> 5, h = i & 31;
        float raw = g_zx[(long)(rowbase + l) * DIP + DTOFF + h] + dt_bias[h];
        float dtv = (raw > 20.f) ? raw : log1pf(expf(raw));
        sdt[l][h] = dtv;
    }
    __syncthreads();

    if (tid < NH) {
        float Ah = -expf(A_log[tid]);
        float cum = 0.f;
#pragma unroll
        for (int l = 0; l < CH; l++) {
            cum += sdt[l][tid] * Ah;
            scum[l][tid] = cum;
        }
        g_cdecay[bc * NH + tid] = expf(cum);
    }
    __syncthreads();

    for (int i = tid; i < CH * NH; i += 256) {
        int h = i >> 7, l = i & 127;
        g_dtT[(bc * NH + h) * CH + l] = sdt[l][h];
        g_cumT[(bc * NH + h) * CH + l] = scum[l][h];
    }
}

// ---------------- CB = C @ B^T per chunk (bf16 mma) ----------------
__global__ __launch_bounds__(256)
void cb_mma()
{
    extern __shared__ __nv_bfloat16 smc[];
    uint32_t cb = smem_u32(smc);
    uint32_t bb = cb + 17408 * 2;
    int bc = blockIdx.x;
    int b = bc / NC, c = bc % NC;
    int rowbase = b * LSEQ + c * CH;
    int tid = threadIdx.x;
    int lane = tid & 31, wid = tid >> 5;
    int wr = wid & 3, wc = wid >> 2;

    const __nv_bfloat16* Cg = g_xcb + (long)rowbase * CONVD + COFF;
    const __nv_bfloat16* Bg = g_xcb + (long)rowbase * CONVD + BOFF;
#pragma unroll
    for (int k = 0; k < 8; k++) {
        int id = tid + k * 256;
        int s = id >> 4, c8 = (id & 15) * 8;
        CPASYNC16(cb + (s * 136 + c8) * 2, Cg + (long)s * CONVD + c8);
        CPASYNC16(bb + (s * 136 + c8) * 2, Bg + (long)s * CONVD + c8);
    }
    CP_COMMIT();
    asm volatile("cp.async.wait_group 0;");
    __syncthreads();

    float acc[2][8][4];
#pragma unroll
    for (int i = 0; i < 2; i++)
#pragma unroll
        for (int j = 0; j < 8; j++)
#pragma unroll
            for (int k = 0; k < 4; k++) acc[i][j][k] = 0.f;

#pragma unroll
    for (int kk = 0; kk < 128; kk += 16) {
        uint32_t a[2][4];
#pragma unroll
        for (int mi = 0; mi < 2; mi++) {
            int arow = wr * 32 + mi * 16 + (lane & 15);
            int acol = kk + (lane >> 4) * 8;
            LDMX4(a[mi][0], a[mi][1], a[mi][2], a[mi][3], cb + (arow * 136 + acol) * 2);
        }
#pragma unroll
        for (int nb = 0; nb < 4; nb++) {
            int brow = wc * 64 + nb * 16 + (lane & 7) + ((lane >> 4) & 1) * 8;
            int bcol = kk + ((lane >> 3) & 1) * 8;
            uint32_t t0, t1, t2, t3;
            LDMX4(t0, t1, t2, t3, bb + (brow * 136 + bcol) * 2);
            uint32_t b0[2] = {t0, t1}, b1[2] = {t2, t3};
#pragma unroll
            for (int mi = 0; mi < 2; mi++) {
                MMA16816(acc[mi][nb * 2], a[mi], b0);
                MMA16816(acc[mi][nb * 2 + 1], a[mi], b1);
            }
        }
    }

    float* CBo = g_CB + (long)bc * CH * CH;
#pragma unroll
    for (int mi = 0; mi < 2; mi++) {
        int r = wr * 32 + mi * 16 + (lane >> 2);
#pragma unroll
        for (int nj = 0; nj < 8; nj++) {
            int cc = wc * 64 + nj * 8 + (lane & 3) * 2;
            *(float2*)&CBo[r * CH + cc] = make_float2(acc[mi][nj][0], acc[mi][nj][1]);
            *(float2*)&CBo[(r + 8) * CH + cc] = make_float2(acc[mi][nj][2], acc[mi][nj][3]);
        }
    }
}

// ---------------- per-chunk end states (bf16 mma, 256 threads, 8 warps 4x2) ----------------
__global__ __launch_bounds__(256)
void states_mma()
{
    extern __shared__ __nv_bfloat16 sms[];
    uint32_t wbase = smem_u32(sms);            // wsx [128][72]
    uint32_t bbase = wbase + 9216 * 2;         // Bb  [128][136]
    __shared__ float ws[CH];

    int bch = blockIdx.x;
    int h = bch % NH;
    int bc = bch / NH;
    int b = bc / NC, c = bc % NC;
    int rowbase = b * LSEQ + c * CH;
    int base = bch * CH;
    int tid = threadIdx.x;
    int lane = tid & 31, wid = tid >> 5;
    int wr = wid & 3, wc = wid >> 2;    // 4x2 warp grid, warp tile 16x64

    if (tid < CH) {
        float clast = g_cumT[base + CH - 1];
        ws[tid] = g_dtT[base + tid] * __expf(clast - g_cumT[base + tid]);
    }

    const __nv_bfloat16* Bg = g_xcb + (long)rowbase * CONVD + BOFF;
#pragma unroll
    for (int k = 0; k < 8; k++) {
        int id = tid + k * 256;
        int s = id >> 4, c8 = (id & 15) * 8;
        CPASYNC16(bbase + (s * 136 + c8) * 2, Bg + (long)s * CONVD + c8);
    }
    CP_COMMIT();
    __syncthreads();     // ws visible to all

    {   // stage ws-scaled x as bf16 [s][p], 2 threads per row
        int s = tid >> 1, p0 = (tid & 1) * 32;
        float w = ws[s];
        const float* xr = &g_xc[(long)(rowbase + s) * CONVD + XOFF + h * DH];
        __nv_bfloat16* dst = sms + s * 72;
#pragma unroll
        for (int p = 0; p < 32; p += 4) {
            float4 v = *(const float4*)&xr[p0 + p];
            __nv_bfloat162* d = (__nv_bfloat162*)&dst[p0 + p];
            d[0] = __nv_bfloat162(__float2bfloat16(v.x * w), __float2bfloat16(v.y * w));
            d[1] = __nv_bfloat162(__float2bfloat16(v.z * w), __float2bfloat16(v.w * w));
        }
    }
    asm volatile("cp.async.wait_group 0;");
    __syncthreads();

    float acc[8][4];
#pragma unroll
    for (int j = 0; j < 8; j++)
#pragma unroll
        for (int k = 0; k < 4; k++) acc[j][k] = 0.f;

#pragma unroll
    for (int kk = 0; kk < 128; kk += 16) {
        uint32_t a[4];
        {
            int srow = kk + (lane & 7) + ((lane >> 4) & 1) * 8;
            int scol = wr * 16 + ((lane >> 3) & 1) * 8;
            LDMX4T(a[0], a[1], a[2], a[3], wbase + (srow * 72 + scol) * 2);
        }
#pragma unroll
        for (int nb = 0; nb < 4; nb++) {
            int nbase = wc * 64 + nb * 16;
            int srow = kk + (lane & 7) + ((lane >> 3) & 1) * 8;
            int scol = nbase + ((lane >> 4) & 1) * 8;
            uint32_t t0, t1, t2, t3;
            LDMX4T(t0, t1, t2, t3, bbase + (srow * 136 + scol) * 2);
            uint32_t b0[2] = {t0, t1}, b1[2] = {t2, t3};
            MMA16816(acc[nb * 2], a, b0);
            MMA16816(acc[nb * 2 + 1], a, b1);
        }
    }

    float* Sp = g_S + (long)bch * DH * DS;
    {
        int r = wr * 16 + (lane >> 2);
#pragma unroll
        for (int nj = 0; nj < 8; nj++) {
            int cc = wc * 64 + nj * 8 + (lane & 3) * 2;
            *(float2*)&Sp[r * DS + cc] = make_float2(acc[nj][0], acc[nj][1]);
            *(float2*)&Sp[(r + 8) * DS + cc] = make_float2(acc[nj][2], acc[nj][3]);
        }
    }
}

// ---------------- inter-chunk recurrence ----------------
__global__ __launch_bounds__(256)
void scan_kernel()
{
    int bh = blockIdx.x >> 3;
    int slice = blockIdx.x & 7;
    int b = bh >> 5, h = bh & 31;
    int off = slice * 1024 + threadIdx.x * 4;
    float4 carry = make_float4(0.f, 0.f, 0.f, 0.f);
    for (int c = 0; c < NC; c++) {
        int bch = (b * NC + c) * NH + h;
        float d = g_cdecay[bch];
        long idx = (long)bch * (DH * DS) + off;
        float4 s = *(const float4*)&g_S[idx];
        *(float4*)&g_prev[idx] = carry;
        carry.x = carry.x * d + s.x;
        carry.y = carry.y * d + s.y;
        carry.z = carry.z * d + s.z;
        carry.w = carry.w * d + s.w;
    }
}

// ---------------- Y = intra + inter + D*x (bf16 mma, 256 threads, 8 warps x 16 rows) ----------------
__global__ __launch_bounds__(256)
void y_mma(const float* __restrict__ Dparam)
{
    extern __shared__ __nv_bfloat16 smy[];
    uint32_t xb = smem_u32(smy);               // phase1: xb [128][72]
    uint32_t ms = xb + 9216 * 2;               // phase1: Ms [128][24]
    uint32_t ec = xb;                          // phase2: ElC [128][136]
    uint32_t pb = xb + 17408 * 2;              // phase2: prevb [64][136]
    __shared__ float cl[CH], dts[CH], Fg[CH], El[CH];

    int bch = blockIdx.x;
    int h = bch % NH;
    int bc = bch / NH;
    int b = bc / NC, c = bc % NC;
    int rowbase = b * LSEQ + c * CH;
    int base = bch * CH;
    int tid = threadIdx.x;
    int lane = tid & 31, wid = tid >> 5;      // 8 warps, warp rows wid*16..+15

    if (tid < CH) {
        float cv = g_cumT[base + tid];
        cl[tid] = cv;
        dts[tid] = g_dtT[base + tid];
        El[tid] = __expf(cv);
    }
    const __nv_bfloat16* xg = g_xcb + (long)rowbase * CONVD + XOFF + h * DH;
#pragma unroll
    for (int k = 0; k < 4; k++) {
        int id = tid + k * 256;
        int s = id >> 3, c8 = (id & 7) * 8;
        CPASYNC16(xb + (s * 72 + c8) * 2, xg + (long)s * CONVD + c8);
    }
    CP_COMMIT();
    __syncthreads();                 // cl visible
    if (tid < CH) Fg[tid] = __expf(cl[tid] - cl[tid & ~7]);
    asm volatile("cp.async.wait_group 0;");
    __syncthreads();

    float acc[8][4];
#pragma unroll
    for (int j = 0; j < 8; j++)
#pragma unroll
        for (int k = 0; k < 4; k++) acc[j][k] = 0.f;

    const float* CBp = g_CB + (long)bc * CH * CH;

    // ---- phase 1: Y_intra ----
    for (int kt = 0; kt < 128; kt += 16) {
        {   // build masked decay tile Ms[l][s-kt], one 8-row group per thread
            int sg = kt + (tid & 15);
            int lb = (tid >> 4) * 8;
            float dsg = dts[sg], csg = cl[sg];
            int scc = sg - kt;
            float e0 = __expf(fminf(cl[lb] - csg, 85.f)) * dsg;
#pragma unroll
            for (int i = 0; i < 8; i++) {
                int lg = lb + i;
                float v = (sg <= lg) ? CBp[lg * CH + sg] * Fg[lg] * e0 : 0.f;
                smy[9216 + lg * 24 + scc] = __float2bfloat16(v);
            }
        }
        __syncthreads();
        if (kt <= wid * 16 + 15) {   // causal tile skip (16-row granularity)
            uint32_t a[4];
            {
                int arow = wid * 16 + (lane & 15);
                int acol = (lane >> 4) * 8;
                LDMX4(a[0], a[1], a[2], a[3], ms + (arow * 24 + acol) * 2);
            }
#pragma unroll
            for (int nb = 0; nb < 4; nb++) {
                int nbase = nb * 16;
                int srow = kt + (lane & 7) + ((lane >> 3) & 1) * 8;
                int scol = nbase + ((lane >> 4) & 1) * 8;
                uint32_t t0, t1, t2, t3;
                LDMX4T(t0, t1, t2, t3, xb + (srow * 72 + scol) * 2);
                uint32_t b0[2] = {t0, t1}, b1[2] = {t2, t3};
                MMA16816(acc[nb * 2], a, b0);
                MMA16816(acc[nb * 2 + 1], a, b1);
            }
        }
        __syncthreads();
    }

    // ---- phase 2 staging: ElC [128][136], prevb [64][136] ----
    {
        int l = tid >> 1, n0 = (tid & 1) * 64;
        float el = El[l];
        const __nv_bfloat16* Cg = g_xcb + (long)(rowbase + l) * CONVD + COFF;
        __nv_bfloat16* dst = smy + l * 136;
#pragma unroll
        for (int n = 0; n < 64; n += 2) {
            __nv_bfloat162 cv = *(const __nv_bfloat162*)&Cg[n0 + n];
            *(__nv_bfloat162*)&dst[n0 + n] = __nv_bfloat162(
                __float2bfloat16(__bfloat162float(cv.x) * el),
                __float2bfloat16(__bfloat162float(cv.y) * el));
        }
        const float* Pv = g_prev + (long)bch * DH * DS;
        int p = tid >> 2, m0 = (tid & 3) * 32;
        __nv_bfloat16* pdst = smy + 17408 + p * 136;
#pragma unroll
        for (int n = 0; n < 32; n += 4) {
            float4 v = *(const float4*)&Pv[p * DS + m0 + n];
            __nv_bfloat162* d = (__nv_bfloat162*)&pdst[m0 + n];
            d[0] = __nv_bfloat162(__float2bfloat16(v.x), __float2bfloat16(v.y));
            d[1] = __nv_bfloat162(__float2bfloat16(v.z), __float2bfloat16(v.w));
        }
    }
    __syncthreads();

    // ---- phase 2: Y_inter = (El*C) @ prev^T ----
#pragma unroll
    for (int nt = 0; nt < 128; nt += 16) {
        uint32_t a[4];
        {
            int arow = wid * 16 + (lane & 15);
            int acol = nt + (lane >> 4) * 8;
            LDMX4(a[0], a[1], a[2], a[3], ec + (arow * 136 + acol) * 2);
        }
#pragma unroll
        for (int nb = 0; nb < 4; nb++) {
            int brow = nb * 16 + (lane & 7) + ((lane >> 4) & 1) * 8;
            int bcol = nt + ((lane >> 3) & 1) * 8;
            uint32_t t0, t1, t2, t3;
            LDMX4(t0, t1, t2, t3, pb + (brow * 136 + bcol) * 2);
            uint32_t b0[2] = {t0, t1}, b1[2] = {t2, t3};
            MMA16816(acc[nb * 2], a, b0);
            MMA16816(acc[nb * 2 + 1], a, b1);
        }
    }

    // ---- epilogue: + D*x, store fp32 y ----
    float Dh = Dparam[h];
    {
        int r = wid * 16 + (lane >> 2);
#pragma unroll
        for (int nj = 0; nj < 8; nj++) {
            int cc = nj * 8 + (lane & 3) * 2;
            {
                int row = rowbase + r;
                float2 xv = *(const float2*)&g_xc[(long)row * CONVD + XOFF + h * DH + cc];
                *(float2*)&g_y[(long)row * DSSM + h * DH + cc] =
                    make_float2(acc[nj][0] + Dh * xv.x, acc[nj][1] + Dh * xv.y);
            }
            {
                int row = rowbase + r + 8;
                float2 xv = *(const float2*)&g_xc[(long)row * CONVD + XOFF + h * DH + cc];
                *(float2*)&g_y[(long)row * DSSM + h * DH + cc] =
                    make_float2(acc[nj][2] + Dh * xv.x, acc[nj][3] + Dh * xv.y);
            }
        }
    }
}

// ---------------- gate + RMSNorm, emits bf16 hi/lo ----------------
__global__ __launch_bounds__(256)
void gatenorm_kernel(const float* __restrict__ norm_w)
{
    int row = blockIdx.x;
    int tid = threadIdx.x;
    float v[8];
    float ss = 0.f;
#pragma unroll
    for (int j = 0; j < 8; j++) {
        int cidx = tid + j * 256;
        float y = g_y[(long)row * DSSM + cidx];
        float z = g_zx[(long)row * DIP + ZOFF + cidx];
        float g = z / (1.f + __expf(-z));
        float yg = y * g;
        v[j] = yg;
        ss += yg * yg;
    }
#pragma unroll
    for (int o = 16; o > 0; o >>= 1) ss += __shfl_xor_sync(0xffffffffu, ss, o);
    __shared__ float red[8];
    __shared__ float rinv;
    if ((tid & 31) == 0) red[tid >> 5] = ss;
    __syncthreads();
    if (tid == 0) {
        float t = 0.f;
#pragma unroll
        for (int i = 0; i < 8; i++) t += red[i];
        rinv = rsqrtf(t / (float)DSSM + 1e-5f);
    }
    __syncthreads();
    float r = rinv;
#pragma unroll
    for (int j = 0; j < 8; j++) {
        int cidx = tid + j * 256;
        float val = v[j] * r * norm_w[cidx];
        __nv_bfloat16 hh = __float2bfloat16(val);
        __nv_bfloat16 ll = __float2bfloat16(val - __bfloat162float(hh));
        g_yhi[(long)row * DSSM + cidx] = hh;
        g_ylo[(long)row * DSSM + cidx] = ll;
    }
}

// ---------------- host launcher ----------------
extern "C" void kernel_launch(void* const* d_in, const int* in_sizes, int n_in,
                              void* d_out, int out_size)
{
    const float* u       = (const float*)d_in[0];
    const float* W_in    = (const float*)d_in[1];
    const float* conv_w  = (const float*)d_in[2];
    const float* conv_b  = (const float*)d_in[3];
    const float* dt_bias = (const float*)d_in[4];
    const float* A_log   = (const float*)d_in[5];
    const float* Dp      = (const float*)d_in[6];
    const float* norm_w  = (const float*)d_in[7];
    const float* W_out   = (const float*)d_in[8];
    float* out = (float*)d_out;

    float *p_zx;
    cudaGetSymbolAddress((void**)&p_zx, g_zx);
    __nv_bfloat16 *p_uhi, *p_ulo, *p_w1hi, *p_w1lo, *p_yhi, *p_ylo, *p_w2hi, *p_w2lo;
    cudaGetSymbolAddress((void**)&p_uhi, g_uhi);
    cudaGetSymbolAddress((void**)&p_ulo, g_ulo);
    cudaGetSymbolAddress((void**)&p_w1hi, g_w1hi);
    cudaGetSymbolAddress((void**)&p_w1lo, g_w1lo);
    cudaGetSymbolAddress((void**)&p_yhi, g_yhi);
    cudaGetSymbolAddress((void**)&p_ylo, g_ylo);
    cudaGetSymbolAddress((void**)&p_w2hi, g_w2hi);
    cudaGetSymbolAddress((void**)&p_w2lo, g_w2lo);

    static int smem_set = 0;
    if (!smem_set) {
        cudaFuncSetAttribute(gemm_bf3, cudaFuncAttributeMaxDynamicSharedMemorySize, 2 * STAGE_ELEMS * 2);
        cudaFuncSetAttribute(cb_mma, cudaFuncAttributeMaxDynamicSharedMemorySize, 69632);
        cudaFuncSetAttribute(states_mma, cudaFuncAttributeMaxDynamicSharedMemorySize, 53248);
        cudaFuncSetAttribute(y_mma, cudaFuncAttributeMaxDynamicSharedMemorySize, 52224);
        smem_set = 1;
    }

    // 0) bf16 hi/lo conversions
    {
        long nq = (long)ROWS * DM / 4;
        cvt_split<<<(nq + 255) / 256, 256>>>(u, p_uhi, p_ulo, nq, nq);
    }
    {
        long nq = (long)DIPPAD * DM / 4, ns = (long)DIP * DM / 4;
        cvt_split<<<(nq + 255) / 256, 256>>>(W_in, p_w1hi, p_w1lo, nq, ns);
    }
    {
        long nq = (long)DM * DSSM / 4;
        cvt_split<<<(nq + 255) / 256, 256>>>(W_out, p_w2hi, p_w2lo, nq, nq);
    }

    // 1) in_proj
    gemm_bf3<<<dim3(DIPPAD / 128, ROWS / 128), 256, 2 * STAGE_ELEMS * 2>>>(
        p_uhi, p_ulo, p_w1hi, p_w1lo, p_zx, ROWS, DIP, DM, DIP);

    // 2) conv + silu
    conv_silu_kernel<<<dim3(CONVD / 256, ROWS / 32), 256>>>(conv_w, conv_b);

    // 3) dt / cumsum
    dtcum_kernel<<<BATCH * NC, 256>>>(dt_bias, A_log);

    // 4) CB
    cb_mma<<<BATCH * NC, 256, 69632>>>();

    // 5) states (256 threads)
    states_mma<<<BATCH * NC * NH, 256, 53248>>>();

    // 6) scan
    scan_kernel<<<BATCH * NH * 8, 256>>>();

    // 7) Y (256 threads)
    y_mma<<<BATCH * NC * NH, 256, 52224>>>(Dp);

    // 8) gate + RMSNorm
    gatenorm_kernel<<<ROWS, 256>>>(norm_w);

    // 9) out_proj
    gemm_bf3<<<dim3(DM / 128, ROWS / 128), 256, 2 * STAGE_ELEMS * 2>>>(
        p_yhi, p_ylo, p_w2hi, p_w2lo, out, ROWS, DM, DSSM, DM);

    (void)in_sizes; (void)n_in; (void)out_size;
}

// round 16
// speedup vs baseline: 1.4345x; 1.2577x over previous
#include <cuda_runtime.h>
#include <cuda_fp16.h>
#include <cstdint>
#include <math.h>

// ---------------- problem constants ----------------
#define BATCH   2
#define LSEQ    2048
#define DM      1024
#define DIP     4384
#define DIPPAD  4480
#define DSSM    2048
#define CONVD   2304
#define NH      32
#define DH      64
#define DS      128
#define CH      128
#define NC      (LSEQ / CH)
#define ROWS    (BATCH * LSEQ)
#define ZOFF    0
#define XBCOFF  2048
#define DTOFF   4352
#define XOFF    0
#define BOFF    2048
#define COFF    2176

// ---------------- scratch ----------------
__device__ float g_zx[ROWS * DIP];
__device__ float g_xc[ROWS * CONVD];
__device__ __half g_xcb[ROWS * CONVD];   // fp16 copy of conv output
__device__ float g_dtT[BATCH * NC * NH * CH];
__device__ float g_cumT[BATCH * NC * NH * CH];
__device__ float g_cdecay[BATCH * NC * NH];
__device__ float g_CB[BATCH * NC * CH * CH];
__device__ float g_S[BATCH * NC * NH * DH * DS];
__device__ float g_prev[BATCH * NC * NH * DH * DS];
__device__ float g_y[ROWS * DSSM];

__device__ __half g_uhi[ROWS * DM];
__device__ __half g_w1hi[DIPPAD * DM], g_w1lo[DIPPAD * DM];
__device__ __half g_yhi[ROWS * DSSM];
__device__ __half g_w2hi[DM * DSSM],  g_w2lo[DM * DSSM];

// ---------------- PTX helpers ----------------
__device__ __forceinline__ uint32_t smem_u32(const void* p) {
    return (uint32_t)__cvta_generic_to_shared(p);
}
#define LDMX4(r0,r1,r2,r3,addr) \
    asm volatile("ldmatrix.sync.aligned.m8n8.x4.shared.b16 {%0,%1,%2,%3}, [%4];" \
                 : "=r"(r0),"=r"(r1),"=r"(r2),"=r"(r3) : "r"(addr))
#define LDMX4T(r0,r1,r2,r3,addr) \
    asm volatile("ldmatrix.sync.aligned.m8n8.x4.trans.shared.b16 {%0,%1,%2,%3}, [%4];" \
                 : "=r"(r0),"=r"(r1),"=r"(r2),"=r"(r3) : "r"(addr))
#define MMA16816(d,a,b) \
    asm volatile("mma.sync.aligned.m16n8k16.row.col.f32.f16.f16.f32 " \
                 "{%0,%1,%2,%3},{%4,%5,%6,%7},{%8,%9},{%0,%1,%2,%3};" \
                 : "+f"((d)[0]),"+f"((d)[1]),"+f"((d)[2]),"+f"((d)[3]) \
                 : "r"((a)[0]),"r"((a)[1]),"r"((a)[2]),"r"((a)[3]),"r"((b)[0]),"r"((b)[1]))
#define CPASYNC16(s,g) \
    asm volatile("cp.async.cg.shared.global [%0], [%1], 16;" :: "r"(s),"l"(g))
#define CP_COMMIT() asm volatile("cp.async.commit_group;")

// ---------------- fp32 -> fp16 hi/lo split (weights) ----------------
__global__ __launch_bounds__(256)
void cvt_split(const float* __restrict__ X, __half* __restrict__ hi,
               __half* __restrict__ lo, long nquad, long nquad_src)
{
    long q = (long)blockIdx.x * 256 + threadIdx.x;
    if (q >= nquad) return;
    float4 v = make_float4(0.f, 0.f, 0.f, 0.f);
    if (q < nquad_src) v = *(const float4*)&X[q * 4];
    __half h0 = __float2half(v.x);
    __half h1 = __float2half(v.y);
    __half h2 = __float2half(v.z);
    __half h3 = __float2half(v.w);
    __half l0 = __float2half(v.x - __half2float(h0));
    __half l1 = __float2half(v.y - __half2float(h1));
    __half l2 = __float2half(v.z - __half2float(h2));
    __half l3 = __float2half(v.w - __half2float(h3));
    __half2* hp = (__half2*)&hi[q * 4];
    __half2* lp = (__half2*)&lo[q * 4];
    hp[0] = __halves2half2(h0, h1); hp[1] = __halves2half2(h2, h3);
    lp[0] = __halves2half2(l0, l1); lp[1] = __halves2half2(l2, l3);
}

// ---------------- fp32 -> fp16 (activations) ----------------
__global__ __launch_bounds__(256)
void cvt_hi(const float* __restrict__ X, __half* __restrict__ hi, long nquad)
{
    long q = (long)blockIdx.x * 256 + threadIdx.x;
    if (q >= nquad) return;
    float4 v = *(const float4*)&X[q * 4];
    __half2* hp = (__half2*)&hi[q * 4];
    hp[0] = __floats2half2_rn(v.x, v.y);
    hp[1] = __floats2half2_rn(v.z, v.w);
}

// ---------------- fp16 split-2 tensor-core GEMM: C = A(fp16) · B(hi+lo)^T ----------------
#define SM_STRIDE 40
#define STAGE_ELEMS 15360

__global__ __launch_bounds__(256)
void gemm_f16(const __half* __restrict__ Ahi,
              const __half* __restrict__ Bhi, const __half* __restrict__ Blo,
              float* __restrict__ C, int M, int N, int K, int ldc)
{
    extern __shared__ __half sm[];
    const uint32_t sbase = smem_u32(sm);
    const int tid = threadIdx.x;
    const int lane = tid & 31, wid = tid >> 5;
    const int wr = wid & 1, wc = wid >> 1;
    const int row0 = blockIdx.y * 128;
    const int col0 = blockIdx.x * 128;

    float acc[4][4][4];
#pragma unroll
    for (int i = 0; i < 4; i++)
#pragma unroll
        for (int j = 0; j < 4; j++)
#pragma unroll
            for (int k = 0; k < 4; k++) acc[i][j][k] = 0.f;

    const int nt = K >> 5;
    const int ch0 = tid, ch1 = tid + 256;
    const int r0c = ch0 >> 2, s0c = (ch0 & 3) * 8;
    const int r1c = ch1 >> 2, s1c = (ch1 & 3) * 8;

    auto issue = [&](int kt, int stage) {
        uint32_t sb = sbase + stage * (STAGE_ELEMS * 2);
        CPASYNC16(sb + (r0c * SM_STRIDE + s0c) * 2, Ahi + (long)(row0 + r0c) * K + kt + s0c);
        CPASYNC16(sb + (r1c * SM_STRIDE + s1c) * 2, Ahi + (long)(row0 + r1c) * K + kt + s1c);
        CPASYNC16(sb + (5120 + r0c * SM_STRIDE + s0c) * 2, Bhi + (long)(col0 + r0c) * K + kt + s0c);
        CPASYNC16(sb + (5120 + r1c * SM_STRIDE + s1c) * 2, Bhi + (long)(col0 + r1c) * K + kt + s1c);
        CPASYNC16(sb + (10240 + r0c * SM_STRIDE + s0c) * 2, Blo + (long)(col0 + r0c) * K + kt + s0c);
        CPASYNC16(sb + (10240 + r1c * SM_STRIDE + s1c) * 2, Blo + (long)(col0 + r1c) * K + kt + s1c);
        CP_COMMIT();
    };

    issue(0, 0);

    for (int it = 0; it < nt; it++) {
        asm volatile("cp.async.wait_group 0;");
        __syncthreads();
        if (it + 1 < nt) issue((it + 1) << 5, (it + 1) & 1);

        uint32_t sb = sbase + (it & 1) * (STAGE_ELEMS * 2);
#pragma unroll
        for (int kk = 0; kk < 32; kk += 16) {
            uint32_t ah[4][4], bh[4][2], bl[4][2];
#pragma unroll
            for (int mi = 0; mi < 4; mi++) {
                int arow = wr * 64 + mi * 16 + (lane & 15);
                int acol = kk + (lane >> 4) * 8;
                LDMX4(ah[mi][0], ah[mi][1], ah[mi][2], ah[mi][3],
                      sb + (arow * SM_STRIDE + acol) * 2);
            }
#pragma unroll
            for (int half = 0; half < 2; half++) {
                int brow = wc * 32 + half * 16 + (lane & 7) + ((lane >> 4) & 1) * 8;
                int bcol = kk + ((lane >> 3) & 1) * 8;
                uint32_t bd = sb + (5120 + brow * SM_STRIDE + bcol) * 2;
                uint32_t t0, t1, t2, t3;
                LDMX4(t0, t1, t2, t3, bd);
                bh[half*2][0] = t0; bh[half*2][1] = t1;
                bh[half*2+1][0] = t2; bh[half*2+1][1] = t3;
                LDMX4(t0, t1, t2, t3, bd + 5120 * 2);
                bl[half*2][0] = t0; bl[half*2][1] = t1;
                bl[half*2+1][0] = t2; bl[half*2+1][1] = t3;
            }
#pragma unroll
            for (int mi = 0; mi < 4; mi++)
#pragma unroll
                for (int nj = 0; nj < 4; nj++)
                    MMA16816(acc[mi][nj], ah[mi], bh[nj]);
#pragma unroll
            for (int mi = 0; mi < 4; mi++)
#pragma unroll
                for (int nj = 0; nj < 4; nj++)
                    MMA16816(acc[mi][nj], ah[mi], bl[nj]);
        }
    }

#pragma unroll
    for (int mi = 0; mi < 4; mi++) {
        int r = row0 + wr * 64 + mi * 16 + (lane >> 2);
#pragma unroll
        for (int nj = 0; nj < 4; nj++) {
            int cc = col0 + wc * 32 + nj * 8 + (lane & 3) * 2;
            if (cc < N) {
                *(float2*)&C[(long)r * ldc + cc] = make_float2(acc[mi][nj][0], acc[mi][nj][1]);
                *(float2*)&C[(long)(r + 8) * ldc + cc] = make_float2(acc[mi][nj][2], acc[mi][nj][3]);
            }
        }
    }
}

// ---------------- conv1d + silu, emits fp32 + fp16 ----------------
__global__ __launch_bounds__(256)
void conv_silu_kernel(const float* __restrict__ conv_w, const float* __restrict__ conv_b)
{
    __shared__ float t[35][256];
    int tid = threadIdx.x;
    int col = blockIdx.x * 256 + tid;
    int rowstart = blockIdx.y * 32;
    int l0 = rowstart & (LSEQ - 1);

#pragma unroll
    for (int r = 0; r < 35; r++) {
        int l = l0 - 3 + r;
        float v = 0.f;
        if (l >= 0) v = g_zx[(long)(rowstart - 3 + r) * DIP + XBCOFF + col];
        t[r][tid] = v;
    }
    __syncthreads();

    float w0 = conv_w[col * 4 + 0], w1 = conv_w[col * 4 + 1];
    float w2 = conv_w[col * 4 + 2], w3 = conv_w[col * 4 + 3];
    float bb = conv_b[col];
#pragma unroll
    for (int r = 0; r < 32; r++) {
        float acc = bb + t[r][tid] * w0 + t[r + 1][tid] * w1
                       + t[r + 2][tid] * w2 + t[r + 3][tid] * w3;
        float s = acc / (1.f + __expf(-acc));
        g_xc[(long)(rowstart + r) * CONVD + col] = s;
        g_xcb[(long)(rowstart + r) * CONVD + col] = __float2half(s);
    }
}

// ---------------- dt softplus + per-chunk cumsum ----------------
__global__ __launch_bounds__(256)
void dtcum_kernel(const float* __restrict__ dt_bias, const float* __restrict__ A_log)
{
    __shared__ float sdt[CH][33];
    __shared__ float scum[CH][33];
    int bc = blockIdx.x;
    int b = bc / NC, c = bc % NC;
    int tid = threadIdx.x;
    int rowbase = b * LSEQ + c * CH;

    for (int i = tid; i < CH * NH; i += 256) {
        int l = i >> 5, h = i & 31;
        float raw = g_zx[(long)(rowbase + l) * DIP + DTOFF + h] + dt_bias[h];
        float dtv = (raw > 20.f) ? raw : log1pf(expf(raw));
        sdt[l][h] = dtv;
    }
    __syncthreads();

    if (tid < NH) {
        float Ah = -expf(A_log[tid]);
        float cum = 0.f;
#pragma unroll
        for (int l = 0; l < CH; l++) {
            cum += sdt[l][tid] * Ah;
            scum[l][tid] = cum;
        }
        g_cdecay[bc * NH + tid] = expf(cum);
    }
    __syncthreads();

    for (int i = tid; i < CH * NH; i += 256) {
        int h = i >> 7, l = i & 127;
        g_dtT[(bc * NH + h) * CH + l] = sdt[l][h];
        g_cumT[(bc * NH + h) * CH + l] = scum[l][h];
    }
}

// ---------------- CB = C @ B^T per chunk (fp16 mma) ----------------
__global__ __launch_bounds__(256)
void cb_mma()
{
    extern __shared__ __half smc[];
    uint32_t cb = smem_u32(smc);
    uint32_t bb = cb + 17408 * 2;
    int bc = blockIdx.x;
    int b = bc / NC, c = bc % NC;
    int rowbase = b * LSEQ + c * CH;
    int tid = threadIdx.x;
    int lane = tid & 31, wid = tid >> 5;
    int wr = wid & 3, wc = wid >> 2;

    const __half* Cg = g_xcb + (long)rowbase * CONVD + COFF;
    const __half* Bg = g_xcb + (long)rowbase * CONVD + BOFF;
#pragma unroll
    for (int k = 0; k < 8; k++) {
        int id = tid + k * 256;
        int s = id >> 4, c8 = (id & 15) * 8;
        CPASYNC16(cb + (s * 136 + c8) * 2, Cg + (long)s * CONVD + c8);
        CPASYNC16(bb + (s * 136 + c8) * 2, Bg + (long)s * CONVD + c8);
    }
    CP_COMMIT();
    asm volatile("cp.async.wait_group 0;");
    __syncthreads();

    float acc[2][8][4];
#pragma unroll
    for (int i = 0; i < 2; i++)
#pragma unroll
        for (int j = 0; j < 8; j++)
#pragma unroll
            for (int k = 0; k < 4; k++) acc[i][j][k] = 0.f;

#pragma unroll
    for (int kk = 0; kk < 128; kk += 16) {
        uint32_t a[2][4];
#pragma unroll
        for (int mi = 0; mi < 2; mi++) {
            int arow = wr * 32 + mi * 16 + (lane & 15);
            int acol = kk + (lane >> 4) * 8;
            LDMX4(a[mi][0], a[mi][1], a[mi][2], a[mi][3], cb + (arow * 136 + acol) * 2);
        }
#pragma unroll
        for (int nb = 0; nb < 4; nb++) {
            int brow = wc * 64 + nb * 16 + (lane & 7) + ((lane >> 4) & 1) * 8;
            int bcol = kk + ((lane >> 3) & 1) * 8;
            uint32_t t0, t1, t2, t3;
            LDMX4(t0, t1, t2, t3, bb + (brow * 136 + bcol) * 2);
            uint32_t b0[2] = {t0, t1}, b1[2] = {t2, t3};
#pragma unroll
            for (int mi = 0; mi < 2; mi++) {
                MMA16816(acc[mi][nb * 2], a[mi], b0);
                MMA16816(acc[mi][nb * 2 + 1], a[mi], b1);
            }
        }
    }

    float* CBo = g_CB + (long)bc * CH * CH;
#pragma unroll
    for (int mi = 0; mi < 2; mi++) {
        int r = wr * 32 + mi * 16 + (lane >> 2);
#pragma unroll
        for (int nj = 0; nj < 8; nj++) {
            int cc = wc * 64 + nj * 8 + (lane & 3) * 2;
            *(float2*)&CBo[r * CH + cc] = make_float2(acc[mi][nj][0], acc[mi][nj][1]);
            *(float2*)&CBo[(r + 8) * CH + cc] = make_float2(acc[mi][nj][2], acc[mi][nj][3]);
        }
    }
}

// ---------------- per-chunk end states (fp16 mma, 256 threads) ----------------
__global__ __launch_bounds__(256)
void states_mma()
{
    extern __shared__ __half sms[];
    uint32_t wbase = smem_u32(sms);            // wsx [128][72]
    uint32_t bbase = wbase + 9216 * 2;         // Bb  [128][136]
    __shared__ float ws[CH];

    int bch = blockIdx.x;
    int h = bch % NH;
    int bc = bch / NH;
    int b = bc / NC, c = bc % NC;
    int rowbase = b * LSEQ + c * CH;
    int base = bch * CH;
    int tid = threadIdx.x;
    int lane = tid & 31, wid = tid >> 5;
    int wr = wid & 3, wc = wid >> 2;

    if (tid < CH) {
        float clast = g_cumT[base + CH - 1];
        ws[tid] = g_dtT[base + tid] * __expf(clast - g_cumT[base + tid]);
    }

    const __half* Bg = g_xcb + (long)rowbase * CONVD + BOFF;
#pragma unroll
    for (int k = 0; k < 8; k++) {
        int id = tid + k * 256;
        int s = id >> 4, c8 = (id & 15) * 8;
        CPASYNC16(bbase + (s * 136 + c8) * 2, Bg + (long)s * CONVD + c8);
    }
    CP_COMMIT();
    __syncthreads();

    {
        int s = tid >> 1, p0 = (tid & 1) * 32;
        float w = ws[s];
        const float* xr = &g_xc[(long)(rowbase + s) * CONVD + XOFF + h * DH];
        __half* dst = sms + s * 72;
#pragma unroll
        for (int p = 0; p < 32; p += 4) {
            float4 v = *(const float4*)&xr[p0 + p];
            __half2* d = (__half2*)&dst[p0 + p];
            d[0] = __floats2half2_rn(v.x * w, v.y * w);
            d[1] = __floats2half2_rn(v.z * w, v.w * w);
        }
    }
    asm volatile("cp.async.wait_group 0;");
    __syncthreads();

    float acc[8][4];
#pragma unroll
    for (int j = 0; j < 8; j++)
#pragma unroll
        for (int k = 0; k < 4; k++) acc[j][k] = 0.f;

#pragma unroll
    for (int kk = 0; kk < 128; kk += 16) {
        uint32_t a[4];
        {
            int srow = kk + (lane & 7) + ((lane >> 4) & 1) * 8;
            int scol = wr * 16 + ((lane >> 3) & 1) * 8;
            LDMX4T(a[0], a[1], a[2], a[3], wbase + (srow * 72 + scol) * 2);
        }
#pragma unroll
        for (int nb = 0; nb < 4; nb++) {
            int nbase = wc * 64 + nb * 16;
            int srow = kk + (lane & 7) + ((lane >> 3) & 1) * 8;
            int scol = nbase + ((lane >> 4) & 1) * 8;
            uint32_t t0, t1, t2, t3;
            LDMX4T(t0, t1, t2, t3, bbase + (srow * 136 + scol) * 2);
            uint32_t b0[2] = {t0, t1}, b1[2] = {t2, t3};
            MMA16816(acc[nb * 2], a, b0);
            MMA16816(acc[nb * 2 + 1], a, b1);
        }
    }

    float* Sp = g_S + (long)bch * DH * DS;
    {
        int r = wr * 16 + (lane >> 2);
#pragma unroll
        for (int nj = 0; nj < 8; nj++) {
            int cc = wc * 64 + nj * 8 + (lane & 3) * 2;
            *(float2*)&Sp[r * DS + cc] = make_float2(acc[nj][0], acc[nj][1]);
            *(float2*)&Sp[(r + 8) * DS + cc] = make_float2(acc[nj][2], acc[nj][3]);
        }
    }
}

// ---------------- inter-chunk recurrence ----------------
__global__ __launch_bounds__(256)
void scan_kernel()
{
    int bh = blockIdx.x >> 3;
    int slice = blockIdx.x & 7;
    int b = bh >> 5, h = bh & 31;
    int off = slice * 1024 + threadIdx.x * 4;
    float4 carry = make_float4(0.f, 0.f, 0.f, 0.f);
    for (int c = 0; c < NC; c++) {
        int bch = (b * NC + c) * NH + h;
        float d = g_cdecay[bch];
        long idx = (long)bch * (DH * DS) + off;
        float4 s = *(const float4*)&g_S[idx];
        *(float4*)&g_prev[idx] = carry;
        carry.x = carry.x * d + s.x;
        carry.y = carry.y * d + s.y;
        carry.z = carry.z * d + s.z;
        carry.w = carry.w * d + s.w;
    }
}

// ---------------- Y = intra + inter + D*x (fp16 mma, 256 threads) ----------------
__global__ __launch_bounds__(256)
void y_mma(const float* __restrict__ Dparam)
{
    extern __shared__ __half smy[];
    uint32_t xb = smem_u32(smy);               // phase1: xb [128][72]
    uint32_t ms = xb + 9216 * 2;               // phase1: Ms [128][24]
    uint32_t ec = xb;                          // phase2: ElC [128][136]
    uint32_t pb = xb + 17408 * 2;              // phase2: prevb [64][136]
    __shared__ float cl[CH], dts[CH], Fg[CH], El[CH];

    int bch = blockIdx.x;
    int h = bch % NH;
    int bc = bch / NH;
    int b = bc / NC, c = bc % NC;
    int rowbase = b * LSEQ + c * CH;
    int base = bch * CH;
    int tid = threadIdx.x;
    int lane = tid & 31, wid = tid >> 5;

    if (tid < CH) {
        float cv = g_cumT[base + tid];
        cl[tid] = cv;
        dts[tid] = g_dtT[base + tid];
        El[tid] = __expf(cv);
    }
    const __half* xg = g_xcb + (long)rowbase * CONVD + XOFF + h * DH;
#pragma unroll
    for (int k = 0; k < 4; k++) {
        int id = tid + k * 256;
        int s = id >> 3, c8 = (id & 7) * 8;
        CPASYNC16(xb + (s * 72 + c8) * 2, xg + (long)s * CONVD + c8);
    }
    CP_COMMIT();
    __syncthreads();
    if (tid < CH) Fg[tid] = __expf(cl[tid] - cl[tid & ~7]);
    asm volatile("cp.async.wait_group 0;");
    __syncthreads();

    float acc[8][4];
#pragma unroll
    for (int j = 0; j < 8; j++)
#pragma unroll
        for (int k = 0; k < 4; k++) acc[j][k] = 0.f;

    const float* CBp = g_CB + (long)bc * CH * CH;

    // ---- phase 1: Y_intra ----
    for (int kt = 0; kt < 128; kt += 16) {
        {
            int sg = kt + (tid & 15);
            int lb = (tid >> 4) * 8;
            float dsg = dts[sg], csg = cl[sg];
            int scc = sg - kt;
            float e0 = __expf(fminf(cl[lb] - csg, 85.f)) * dsg;
#pragma unroll
            for (int i = 0; i < 8; i++) {
                int lg = lb + i;
                float v = (sg <= lg) ? CBp[lg * CH + sg] * Fg[lg] * e0 : 0.f;
                smy[9216 + lg * 24 + scc] = __float2half(v);
            }
        }
        __syncthreads();
        if (kt <= wid * 16 + 15) {
            uint32_t a[4];
            {
                int arow = wid * 16 + (lane & 15);
                int acol = (lane >> 4) * 8;
                LDMX4(a[0], a[1], a[2], a[3], ms + (arow * 24 + acol) * 2);
            }
#pragma unroll
            for (int nb = 0; nb < 4; nb++) {
                int nbase = nb * 16;
                int srow = kt + (lane & 7) + ((lane >> 3) & 1) * 8;
                int scol = nbase + ((lane >> 4) & 1) * 8;
                uint32_t t0, t1, t2, t3;
                LDMX4T(t0, t1, t2, t3, xb + (srow * 72 + scol) * 2);
                uint32_t b0[2] = {t0, t1}, b1[2] = {t2, t3};
                MMA16816(acc[nb * 2], a, b0);
                MMA16816(acc[nb * 2 + 1], a, b1);
            }
        }
        __syncthreads();
    }

    // ---- phase 2 staging ----
    {
        int l = tid >> 1, n0 = (tid & 1) * 64;
        float el = El[l];
        const __half* Cg = g_xcb + (long)(rowbase + l) * CONVD + COFF;
        __half* dst = smy + l * 136;
#pragma unroll
        for (int n = 0; n < 64; n += 2) {
            __half2 cv = *(const __half2*)&Cg[n0 + n];
            *(__half2*)&dst[n0 + n] = __floats2half2_rn(
                __half2float(cv.x) * el, __half2float(cv.y) * el);
        }
        const float* Pv = g_prev + (long)bch * DH * DS;
        int p = tid >> 2, m0 = (tid & 3) * 32;
        __half* pdst = smy + 17408 + p * 136;
#pragma unroll
        for (int n = 0; n < 32; n += 4) {
            float4 v = *(const float4*)&Pv[p * DS + m0 + n];
            __half2* d = (__half2*)&pdst[m0 + n];
            d[0] = __floats2half2_rn(v.x, v.y);
            d[1] = __floats2half2_rn(v.z, v.w);
        }
    }
    __syncthreads();

    // ---- phase 2: Y_inter ----
#pragma unroll
    for (int nt = 0; nt < 128; nt += 16) {
        uint32_t a[4];
        {
            int arow = wid * 16 + (lane & 15);
            int acol = nt + (lane >> 4) * 8;
            LDMX4(a[0], a[1], a[2], a[3], ec + (arow * 136 + acol) * 2);
        }
#pragma unroll
        for (int nb = 0; nb < 4; nb++) {
            int brow = nb * 16 + (lane & 7) + ((lane >> 4) & 1) * 8;
            int bcol = nt + ((lane >> 3) & 1) * 8;
            uint32_t t0, t1, t2, t3;
            LDMX4(t0, t1, t2, t3, pb + (brow * 136 + bcol) * 2);
            uint32_t b0[2] = {t0, t1}, b1[2] = {t2, t3};
            MMA16816(acc[nb * 2], a, b0);
            MMA16816(acc[nb * 2 + 1], a, b1);
        }
    }

    // ---- epilogue ----
    float Dh = Dparam[h];
    {
        int r = wid * 16 + (lane >> 2);
#pragma unroll
        for (int nj = 0; nj < 8; nj++) {
            int cc = nj * 8 + (lane & 3) * 2;
            {
                int row = rowbase + r;
                float2 xv = *(const float2*)&g_xc[(long)row * CONVD + XOFF + h * DH + cc];
                *(float2*)&g_y[(long)row * DSSM + h * DH + cc] =
                    make_float2(acc[nj][0] + Dh * xv.x, acc[nj][1] + Dh * xv.y);
            }
            {
                int row = rowbase + r + 8;
                float2 xv = *(const float2*)&g_xc[(long)row * CONVD + XOFF + h * DH + cc];
                *(float2*)&g_y[(long)row * DSSM + h * DH + cc] =
                    make_float2(acc[nj][2] + Dh * xv.x, acc[nj][3] + Dh * xv.y);
            }
        }
    }
}

// ---------------- gate + RMSNorm, emits fp16 ----------------
__global__ __launch_bounds__(256)
void gatenorm_kernel(const float* __restrict__ norm_w)
{
    int row = blockIdx.x;
    int tid = threadIdx.x;
    float v[8];
    float ss = 0.f;
#pragma unroll
    for (int j = 0; j < 8; j++) {
        int cidx = tid + j * 256;
        float y = g_y[(long)row * DSSM + cidx];
        float z = g_zx[(long)row * DIP + ZOFF + cidx];
        float g = z / (1.f + __expf(-z));
        float yg = y * g;
        v[j] = yg;
        ss += yg * yg;
    }
#pragma unroll
    for (int o = 16; o > 0; o >>= 1) ss += __shfl_xor_sync(0xffffffffu, ss, o);
    __shared__ float red[8];
    __shared__ float rinv;
    if ((tid & 31) == 0) red[tid >> 5] = ss;
    __syncthreads();
    if (tid == 0) {
        float t = 0.f;
#pragma unroll
        for (int i = 0; i < 8; i++) t += red[i];
        rinv = rsqrtf(t / (float)DSSM + 1e-5f);
    }
    __syncthreads();
    float r = rinv;
#pragma unroll
    for (int j = 0; j < 8; j++) {
        int cidx = tid + j * 256;
        float val = v[j] * r * norm_w[cidx];
        g_yhi[(long)row * DSSM + cidx] = __float2half(val);
    }
}

// ---------------- host launcher ----------------
extern "C" void kernel_launch(void* const* d_in, const int* in_sizes, int n_in,
                              void* d_out, int out_size)
{
    const float* u       = (const float*)d_in[0];
    const float* W_in    = (const float*)d_in[1];
    const float* conv_w  = (const float*)d_in[2];
    const float* conv_b  = (const float*)d_in[3];
    const float* dt_bias = (const float*)d_in[4];
    const float* A_log   = (const float*)d_in[5];
    const float* Dp      = (const float*)d_in[6];
    const float* norm_w  = (const float*)d_in[7];
    const float* W_out   = (const float*)d_in[8];
    float* out = (float*)d_out;

    float *p_zx;
    cudaGetSymbolAddress((void**)&p_zx, g_zx);
    __half *p_uhi, *p_w1hi, *p_w1lo, *p_yhi, *p_w2hi, *p_w2lo;
    cudaGetSymbolAddress((void**)&p_uhi, g_uhi);
    cudaGetSymbolAddress((void**)&p_w1hi, g_w1hi);
    cudaGetSymbolAddress((void**)&p_w1lo, g_w1lo);
    cudaGetSymbolAddress((void**)&p_yhi, g_yhi);
    cudaGetSymbolAddress((void**)&p_w2hi, g_w2hi);
    cudaGetSymbolAddress((void**)&p_w2lo, g_w2lo);

    static int smem_set = 0;
    if (!smem_set) {
        cudaFuncSetAttribute(gemm_f16, cudaFuncAttributeMaxDynamicSharedMemorySize, 2 * STAGE_ELEMS * 2);
        cudaFuncSetAttribute(cb_mma, cudaFuncAttributeMaxDynamicSharedMemorySize, 69632);
        cudaFuncSetAttribute(states_mma, cudaFuncAttributeMaxDynamicSharedMemorySize, 53248);
        cudaFuncSetAttribute(y_mma, cudaFuncAttributeMaxDynamicSharedMemorySize, 52224);
        smem_set = 1;
    }

    // 0) conversions: u -> fp16; W_in/W_out -> fp16 hi/lo
    {
        long nq = (long)ROWS * DM / 4;
        cvt_hi<<<(nq + 255) / 256, 256>>>(u, p_uhi, nq);
    }
    {
        long nq = (long)DIPPAD * DM / 4, ns = (long)DIP * DM / 4;
        cvt_split<<<(nq + 255) / 256, 256>>>(W_in, p_w1hi, p_w1lo, nq, ns);
    }
    {
        long nq = (long)DM * DSSM / 4;
        cvt_split<<<(nq + 255) / 256, 256>>>(W_out, p_w2hi, p_w2lo, nq, nq);
    }

    // 1) in_proj (fp16 split-2)
    gemm_f16<<<dim3(DIPPAD / 128, ROWS / 128), 256, 2 * STAGE_ELEMS * 2>>>(
        p_uhi, p_w1hi, p_w1lo, p_zx, ROWS, DIP, DM, DIP);

    // 2) conv + silu
    conv_silu_kernel<<<dim3(CONVD / 256, ROWS / 32), 256>>>(conv_w, conv_b);

    // 3) dt / cumsum
    dtcum_kernel<<<BATCH * NC, 256>>>(dt_bias, A_log);

    // 4) CB
    cb_mma<<<BATCH * NC, 256, 69632>>>();

    // 5) states
    states_mma<<<BATCH * NC * NH, 256, 53248>>>();

    // 6) scan
    scan_kernel<<<BATCH * NH * 8, 256>>>();

    // 7) Y
    y_mma<<<BATCH * NC * NH, 256, 52224>>>(Dp);

    // 8) gate + RMSNorm
    gatenorm_kernel<<<ROWS, 256>>>(norm_w);

    // 9) out_proj (fp16 split-2)
    gemm_f16<<<dim3(DM / 128, ROWS / 128), 256, 2 * STAGE_ELEMS * 2>>>(
        p_yhi, p_w2hi, p_w2lo, out, ROWS, DM, DSSM, DM);

    (void)in_sizes; (void)n_in; (void)out_size;
}

// round 17
// speedup vs baseline: 1.9209x; 1.3391x over previous
#include <cuda_runtime.h>
#include <cuda_fp16.h>
#include <cstdint>
#include <math.h>

// ---------------- problem constants ----------------
#define BATCH   2
#define LSEQ    2048
#define DM      1024
#define DIP     4384
#define DIPPAD  4480
#define DSSM    2048
#define CONVD   2304
#define NH      32
#define DH      64
#define DS      128
#define CH      128
#define NC      (LSEQ / CH)
#define ROWS    (BATCH * LSEQ)
#define ZOFF    0
#define XBCOFF  2048
#define DTOFF   4352
#define XOFF    0
#define BOFF    2048
#define COFF    2176

// ---------------- scratch ----------------
__device__ float g_zx[ROWS * DIP];
__device__ float g_xc[ROWS * CONVD];
__device__ __half g_xcb[ROWS * CONVD];
__device__ float g_dtT[BATCH * NC * NH * CH];
__device__ float g_cumT[BATCH * NC * NH * CH];
__device__ float g_cdecay[BATCH * NC * NH];
__device__ float g_CB[BATCH * NC * CH * CH];
__device__ float g_S[BATCH * NC * NH * DH * DS];
__device__ float g_prev[BATCH * NC * NH * DH * DS];
__device__ float g_y[ROWS * DSSM];

__device__ __half g_uhi[ROWS * DM];
__device__ __half g_w1hi[DIPPAD * DM];
__device__ __half g_yhi[ROWS * DSSM];
__device__ __half g_w2hi[DM * DSSM];

// ---------------- PTX helpers ----------------
__device__ __forceinline__ uint32_t smem_u32(const void* p) {
    return (uint32_t)__cvta_generic_to_shared(p);
}
#define LDMX4(r0,r1,r2,r3,addr) \
    asm volatile("ldmatrix.sync.aligned.m8n8.x4.shared.b16 {%0,%1,%2,%3}, [%4];" \
                 : "=r"(r0),"=r"(r1),"=r"(r2),"=r"(r3) : "r"(addr))
#define LDMX4T(r0,r1,r2,r3,addr) \
    asm volatile("ldmatrix.sync.aligned.m8n8.x4.trans.shared.b16 {%0,%1,%2,%3}, [%4];" \
                 : "=r"(r0),"=r"(r1),"=r"(r2),"=r"(r3) : "r"(addr))
#define MMA16816(d,a,b) \
    asm volatile("mma.sync.aligned.m16n8k16.row.col.f32.f16.f16.f32 " \
                 "{%0,%1,%2,%3},{%4,%5,%6,%7},{%8,%9},{%0,%1,%2,%3};" \
                 : "+f"((d)[0]),"+f"((d)[1]),"+f"((d)[2]),"+f"((d)[3]) \
                 : "r"((a)[0]),"r"((a)[1]),"r"((a)[2]),"r"((a)[3]),"r"((b)[0]),"r"((b)[1]))
#define CPASYNC16(s,g) \
    asm volatile("cp.async.cg.shared.global [%0], [%1], 16;" :: "r"(s),"l"(g))
#define CP_COMMIT() asm volatile("cp.async.commit_group;")

// ---------------- fp32 -> fp16 (padded variant for weights) ----------------
__global__ __launch_bounds__(256)
void cvt_hi_pad(const float* __restrict__ X, __half* __restrict__ hi,
                long nquad, long nquad_src)
{
    long q = (long)blockIdx.x * 256 + threadIdx.x;
    if (q >= nquad) return;
    float4 v = make_float4(0.f, 0.f, 0.f, 0.f);
    if (q < nquad_src) v = *(const float4*)&X[q * 4];
    __half2* hp = (__half2*)&hi[q * 4];
    hp[0] = __floats2half2_rn(v.x, v.y);
    hp[1] = __floats2half2_rn(v.z, v.w);
}

// ---------------- fp16 x fp16 tensor-core GEMM: C = A · B^T ----------------
// 128x128 tile, BK=32, 2-stage. smem stage: A[128][40], B[128][40] (10240 elems).
#define SM_STRIDE 40
#define STAGE_ELEMS 10240

__global__ __launch_bounds__(256)
void gemm_f16(const __half* __restrict__ Ahi,
              const __half* __restrict__ Bhi,
              float* __restrict__ C, int M, int N, int K, int ldc)
{
    extern __shared__ __half sm[];
    const uint32_t sbase = smem_u32(sm);
    const int tid = threadIdx.x;
    const int lane = tid & 31, wid = tid >> 5;
    const int wr = wid & 1, wc = wid >> 1;
    const int row0 = blockIdx.y * 128;
    const int col0 = blockIdx.x * 128;

    float acc[4][4][4];
#pragma unroll
    for (int i = 0; i < 4; i++)
#pragma unroll
        for (int j = 0; j < 4; j++)
#pragma unroll
            for (int k = 0; k < 4; k++) acc[i][j][k] = 0.f;

    const int nt = K >> 5;
    const int ch0 = tid, ch1 = tid + 256;
    const int r0c = ch0 >> 2, s0c = (ch0 & 3) * 8;
    const int r1c = ch1 >> 2, s1c = (ch1 & 3) * 8;

    auto issue = [&](int kt, int stage) {
        uint32_t sb = sbase + stage * (STAGE_ELEMS * 2);
        CPASYNC16(sb + (r0c * SM_STRIDE + s0c) * 2, Ahi + (long)(row0 + r0c) * K + kt + s0c);
        CPASYNC16(sb + (r1c * SM_STRIDE + s1c) * 2, Ahi + (long)(row0 + r1c) * K + kt + s1c);
        CPASYNC16(sb + (5120 + r0c * SM_STRIDE + s0c) * 2, Bhi + (long)(col0 + r0c) * K + kt + s0c);
        CPASYNC16(sb + (5120 + r1c * SM_STRIDE + s1c) * 2, Bhi + (long)(col0 + r1c) * K + kt + s1c);
        CP_COMMIT();
    };

    issue(0, 0);

    for (int it = 0; it < nt; it++) {
        asm volatile("cp.async.wait_group 0;");
        __syncthreads();
        if (it + 1 < nt) issue((it + 1) << 5, (it + 1) & 1);

        uint32_t sb = sbase + (it & 1) * (STAGE_ELEMS * 2);
#pragma unroll
        for (int kk = 0; kk < 32; kk += 16) {
            uint32_t ah[4][4], bh[4][2];
#pragma unroll
            for (int mi = 0; mi < 4; mi++) {
                int arow = wr * 64 + mi * 16 + (lane & 15);
                int acol = kk + (lane >> 4) * 8;
                LDMX4(ah[mi][0], ah[mi][1], ah[mi][2], ah[mi][3],
                      sb + (arow * SM_STRIDE + acol) * 2);
            }
#pragma unroll
            for (int half = 0; half < 2; half++) {
                int brow = wc * 32 + half * 16 + (lane & 7) + ((lane >> 4) & 1) * 8;
                int bcol = kk + ((lane >> 3) & 1) * 8;
                uint32_t t0, t1, t2, t3;
                LDMX4(t0, t1, t2, t3, sb + (5120 + brow * SM_STRIDE + bcol) * 2);
                bh[half*2][0] = t0; bh[half*2][1] = t1;
                bh[half*2+1][0] = t2; bh[half*2+1][1] = t3;
            }
#pragma unroll
            for (int mi = 0; mi < 4; mi++)
#pragma unroll
                for (int nj = 0; nj < 4; nj++)
                    MMA16816(acc[mi][nj], ah[mi], bh[nj]);
        }
    }

#pragma unroll
    for (int mi = 0; mi < 4; mi++) {
        int r = row0 + wr * 64 + mi * 16 + (lane >> 2);
#pragma unroll
        for (int nj = 0; nj < 4; nj++) {
            int cc = col0 + wc * 32 + nj * 8 + (lane & 3) * 2;
            if (cc < N) {
                *(float2*)&C[(long)r * ldc + cc] = make_float2(acc[mi][nj][0], acc[mi][nj][1]);
                *(float2*)&C[(long)(r + 8) * ldc + cc] = make_float2(acc[mi][nj][2], acc[mi][nj][3]);
            }
        }
    }
}

// ---------------- conv1d + silu, emits fp32 + fp16 ----------------
__global__ __launch_bounds__(256)
void conv_silu_kernel(const float* __restrict__ conv_w, const float* __restrict__ conv_b)
{
    __shared__ float t[35][256];
    int tid = threadIdx.x;
    int col = blockIdx.x * 256 + tid;
    int rowstart = blockIdx.y * 32;
    int l0 = rowstart & (LSEQ - 1);

#pragma unroll
    for (int r = 0; r < 35; r++) {
        int l = l0 - 3 + r;
        float v = 0.f;
        if (l >= 0) v = g_zx[(long)(rowstart - 3 + r) * DIP + XBCOFF + col];
        t[r][tid] = v;
    }
    __syncthreads();

    float w0 = conv_w[col * 4 + 0], w1 = conv_w[col * 4 + 1];
    float w2 = conv_w[col * 4 + 2], w3 = conv_w[col * 4 + 3];
    float bb = conv_b[col];
#pragma unroll
    for (int r = 0; r < 32; r++) {
        float acc = bb + t[r][tid] * w0 + t[r + 1][tid] * w1
                       + t[r + 2][tid] * w2 + t[r + 3][tid] * w3;
        float s = acc / (1.f + __expf(-acc));
        g_xc[(long)(rowstart + r) * CONVD + col] = s;
        g_xcb[(long)(rowstart + r) * CONVD + col] = __float2half(s);
    }
}

// ---------------- dt softplus + per-chunk cumsum ----------------
__global__ __launch_bounds__(256)
void dtcum_kernel(const float* __restrict__ dt_bias, const float* __restrict__ A_log)
{
    __shared__ float sdt[CH][33];
    __shared__ float scum[CH][33];
    int bc = blockIdx.x;
    int b = bc / NC, c = bc % NC;
    int tid = threadIdx.x;
    int rowbase = b * LSEQ + c * CH;

    for (int i = tid; i < CH * NH; i += 256) {
        int l = i >> 5, h = i & 31;
        float raw = g_zx[(long)(rowbase + l) * DIP + DTOFF + h] + dt_bias[h];
        float dtv = (raw > 20.f) ? raw : log1pf(expf(raw));
        sdt[l][h] = dtv;
    }
    __syncthreads();

    if (tid < NH) {
        float Ah = -expf(A_log[tid]);
        float cum = 0.f;
#pragma unroll
        for (int l = 0; l < CH; l++) {
            cum += sdt[l][tid] * Ah;
            scum[l][tid] = cum;
        }
        g_cdecay[bc * NH + tid] = expf(cum);
    }
    __syncthreads();

    for (int i = tid; i < CH * NH; i += 256) {
        int h = i >> 7, l = i & 127;
        g_dtT[(bc * NH + h) * CH + l] = sdt[l][h];
        g_cumT[(bc * NH + h) * CH + l] = scum[l][h];
    }
}

// ---------------- CB = C @ B^T per chunk (fp16 mma) ----------------
__global__ __launch_bounds__(256)
void cb_mma()
{
    extern __shared__ __half smc[];
    uint32_t cb = smem_u32(smc);
    uint32_t bb = cb + 17408 * 2;
    int bc = blockIdx.x;
    int b = bc / NC, c = bc % NC;
    int rowbase = b * LSEQ + c * CH;
    int tid = threadIdx.x;
    int lane = tid & 31, wid = tid >> 5;
    int wr = wid & 3, wc = wid >> 2;

    const __half* Cg = g_xcb + (long)rowbase * CONVD + COFF;
    const __half* Bg = g_xcb + (long)rowbase * CONVD + BOFF;
#pragma unroll
    for (int k = 0; k < 8; k++) {
        int id = tid + k * 256;
        int s = id >> 4, c8 = (id & 15) * 8;
        CPASYNC16(cb + (s * 136 + c8) * 2, Cg + (long)s * CONVD + c8);
        CPASYNC16(bb + (s * 136 + c8) * 2, Bg + (long)s * CONVD + c8);
    }
    CP_COMMIT();
    asm volatile("cp.async.wait_group 0;");
    __syncthreads();

    float acc[2][8][4];
#pragma unroll
    for (int i = 0; i < 2; i++)
#pragma unroll
        for (int j = 0; j < 8; j++)
#pragma unroll
            for (int k = 0; k < 4; k++) acc[i][j][k] = 0.f;

#pragma unroll
    for (int kk = 0; kk < 128; kk += 16) {
        uint32_t a[2][4];
#pragma unroll
        for (int mi = 0; mi < 2; mi++) {
            int arow = wr * 32 + mi * 16 + (lane & 15);
            int acol = kk + (lane >> 4) * 8;
            LDMX4(a[mi][0], a[mi][1], a[mi][2], a[mi][3], cb + (arow * 136 + acol) * 2);
        }
#pragma unroll
        for (int nb = 0; nb < 4; nb++) {
            int brow = wc * 64 + nb * 16 + (lane & 7) + ((lane >> 4) & 1) * 8;
            int bcol = kk + ((lane >> 3) & 1) * 8;
            uint32_t t0, t1, t2, t3;
            LDMX4(t0, t1, t2, t3, bb + (brow * 136 + bcol) * 2);
            uint32_t b0[2] = {t0, t1}, b1[2] = {t2, t3};
#pragma unroll
            for (int mi = 0; mi < 2; mi++) {
                MMA16816(acc[mi][nb * 2], a[mi], b0);
                MMA16816(acc[mi][nb * 2 + 1], a[mi], b1);
            }
        }
    }

    float* CBo = g_CB + (long)bc * CH * CH;
#pragma unroll
    for (int mi = 0; mi < 2; mi++) {
        int r = wr * 32 + mi * 16 + (lane >> 2);
#pragma unroll
        for (int nj = 0; nj < 8; nj++) {
            int cc = wc * 64 + nj * 8 + (lane & 3) * 2;
            *(float2*)&CBo[r * CH + cc] = make_float2(acc[mi][nj][0], acc[mi][nj][1]);
            *(float2*)&CBo[(r + 8) * CH + cc] = make_float2(acc[mi][nj][2], acc[mi][nj][3]);
        }
    }
}

// ---------------- per-chunk end states (fp16 mma, 256 threads) ----------------
__global__ __launch_bounds__(256)
void states_mma()
{
    extern __shared__ __half sms[];
    uint32_t wbase = smem_u32(sms);            // wsx [128][72]
    uint32_t bbase = wbase + 9216 * 2;         // Bb  [128][136]
    __shared__ float ws[CH];

    int bch = blockIdx.x;
    int h = bch % NH;
    int bc = bch / NH;
    int b = bc / NC, c = bc % NC;
    int rowbase = b * LSEQ + c * CH;
    int base = bch * CH;
    int tid = threadIdx.x;
    int lane = tid & 31, wid = tid >> 5;
    int wr = wid & 3, wc = wid >> 2;

    if (tid < CH) {
        float clast = g_cumT[base + CH - 1];
        ws[tid] = g_dtT[base + tid] * __expf(clast - g_cumT[base + tid]);
    }

    const __half* Bg = g_xcb + (long)rowbase * CONVD + BOFF;
#pragma unroll
    for (int k = 0; k < 8; k++) {
        int id = tid + k * 256;
        int s = id >> 4, c8 = (id & 15) * 8;
        CPASYNC16(bbase + (s * 136 + c8) * 2, Bg + (long)s * CONVD + c8);
    }
    CP_COMMIT();
    __syncthreads();

    {
        int s = tid >> 1, p0 = (tid & 1) * 32;
        float w = ws[s];
        const float* xr = &g_xc[(long)(rowbase + s) * CONVD + XOFF + h * DH];
        __half* dst = sms + s * 72;
#pragma unroll
        for (int p = 0; p < 32; p += 4) {
            float4 v = *(const float4*)&xr[p0 + p];
            __half2* d = (__half2*)&dst[p0 + p];
            d[0] = __floats2half2_rn(v.x * w, v.y * w);
            d[1] = __floats2half2_rn(v.z * w, v.w * w);
        }
    }
    asm volatile("cp.async.wait_group 0;");
    __syncthreads();

    float acc[8][4];
#pragma unroll
    for (int j = 0; j < 8; j++)
#pragma unroll
        for (int k = 0; k < 4; k++) acc[j][k] = 0.f;

#pragma unroll
    for (int kk = 0; kk < 128; kk += 16) {
        uint32_t a[4];
        {
            int srow = kk + (lane & 7) + ((lane >> 4) & 1) * 8;
            int scol = wr * 16 + ((lane >> 3) & 1) * 8;
            LDMX4T(a[0], a[1], a[2], a[3], wbase + (srow * 72 + scol) * 2);
        }
#pragma unroll
        for (int nb = 0; nb < 4; nb++) {
            int nbase = wc * 64 + nb * 16;
            int srow = kk + (lane & 7) + ((lane >> 3) & 1) * 8;
            int scol = nbase + ((lane >> 4) & 1) * 8;
            uint32_t t0, t1, t2, t3;
            LDMX4T(t0, t1, t2, t3, bbase + (srow * 136 + scol) * 2);
            uint32_t b0[2] = {t0, t1}, b1[2] = {t2, t3};
            MMA16816(acc[nb * 2], a, b0);
            MMA16816(acc[nb * 2 + 1], a, b1);
        }
    }

    float* Sp = g_S + (long)bch * DH * DS;
    {
        int r = wr * 16 + (lane >> 2);
#pragma unroll
        for (int nj = 0; nj < 8; nj++) {
            int cc = wc * 64 + nj * 8 + (lane & 3) * 2;
            *(float2*)&Sp[r * DS + cc] = make_float2(acc[nj][0], acc[nj][1]);
            *(float2*)&Sp[(r + 8) * DS + cc] = make_float2(acc[nj][2], acc[nj][3]);
        }
    }
}

// ---------------- inter-chunk recurrence ----------------
__global__ __launch_bounds__(256)
void scan_kernel()
{
    int bh = blockIdx.x >> 3;
    int slice = blockIdx.x & 7;
    int b = bh >> 5, h = bh & 31;
    int off = slice * 1024 + threadIdx.x * 4;
    float4 carry = make_float4(0.f, 0.f, 0.f, 0.f);
    for (int c = 0; c < NC; c++) {
        int bch = (b * NC + c) * NH + h;
        float d = g_cdecay[bch];
        long idx = (long)bch * (DH * DS) + off;
        float4 s = *(const float4*)&g_S[idx];
        *(float4*)&g_prev[idx] = carry;
        carry.x = carry.x * d + s.x;
        carry.y = carry.y * d + s.y;
        carry.z = carry.z * d + s.z;
        carry.w = carry.w * d + s.w;
    }
}

// ---------------- Y = intra + inter + D*x (fp16 mma, 256 threads) ----------------
__global__ __launch_bounds__(256)
void y_mma(const float* __restrict__ Dparam)
{
    extern __shared__ __half smy[];
    uint32_t xb = smem_u32(smy);               // phase1: xb [128][72]
    uint32_t ms = xb + 9216 * 2;               // phase1: Ms [128][24]
    uint32_t ec = xb;                          // phase2: ElC [128][136]
    uint32_t pb = xb + 17408 * 2;              // phase2: prevb [64][136]
    __shared__ float cl[CH], dts[CH], Fg[CH], El[CH];

    int bch = blockIdx.x;
    int h = bch % NH;
    int bc = bch / NH;
    int b = bc / NC, c = bc % NC;
    int rowbase = b * LSEQ + c * CH;
    int base = bch * CH;
    int tid = threadIdx.x;
    int lane = tid & 31, wid = tid >> 5;

    if (tid < CH) {
        float cv = g_cumT[base + tid];
        cl[tid] = cv;
        dts[tid] = g_dtT[base + tid];
        El[tid] = __expf(cv);
    }
    const __half* xg = g_xcb + (long)rowbase * CONVD + XOFF + h * DH;
#pragma unroll
    for (int k = 0; k < 4; k++) {
        int id = tid + k * 256;
        int s = id >> 3, c8 = (id & 7) * 8;
        CPASYNC16(xb + (s * 72 + c8) * 2, xg + (long)s * CONVD + c8);
    }
    CP_COMMIT();
    __syncthreads();
    if (tid < CH) Fg[tid] = __expf(cl[tid] - cl[tid & ~7]);
    asm volatile("cp.async.wait_group 0;");
    __syncthreads();

    float acc[8][4];
#pragma unroll
    for (int j = 0; j < 8; j++)
#pragma unroll
        for (int k = 0; k < 4; k++) acc[j][k] = 0.f;

    const float* CBp = g_CB + (long)bc * CH * CH;

    // ---- phase 1: Y_intra ----
    for (int kt = 0; kt < 128; kt += 16) {
        {
            int sg = kt + (tid & 15);
            int lb = (tid >> 4) * 8;
            float dsg = dts[sg], csg = cl[sg];
            int scc = sg - kt;
            float e0 = __expf(fminf(cl[lb] - csg, 85.f)) * dsg;
#pragma unroll
            for (int i = 0; i < 8; i++) {
                int lg = lb + i;
                float v = (sg <= lg) ? CBp[lg * CH + sg] * Fg[lg] * e0 : 0.f;
                smy[9216 + lg * 24 + scc] = __float2half(v);
            }
        }
        __syncthreads();
        if (kt <= wid * 16 + 15) {
            uint32_t a[4];
            {
                int arow = wid * 16 + (lane & 15);
                int acol = (lane >> 4) * 8;
                LDMX4(a[0], a[1], a[2], a[3], ms + (arow * 24 + acol) * 2);
            }
#pragma unroll
            for (int nb = 0; nb < 4; nb++) {
                int nbase = nb * 16;
                int srow = kt + (lane & 7) + ((lane >> 3) & 1) * 8;
                int scol = nbase + ((lane >> 4) & 1) * 8;
                uint32_t t0, t1, t2, t3;
                LDMX4T(t0, t1, t2, t3, xb + (srow * 72 + scol) * 2);
                uint32_t b0[2] = {t0, t1}, b1[2] = {t2, t3};
                MMA16816(acc[nb * 2], a, b0);
                MMA16816(acc[nb * 2 + 1], a, b1);
            }
        }
        __syncthreads();
    }

    // ---- phase 2 staging ----
    {
        int l = tid >> 1, n0 = (tid & 1) * 64;
        float el = El[l];
        const __half* Cg = g_xcb + (long)(rowbase + l) * CONVD + COFF;
        __half* dst = smy + l * 136;
#pragma unroll
        for (int n = 0; n < 64; n += 2) {
            __half2 cv = *(const __half2*)&Cg[n0 + n];
            *(__half2*)&dst[n0 + n] = __floats2half2_rn(
                __half2float(cv.x) * el, __half2float(cv.y) * el);
        }
        const float* Pv = g_prev + (long)bch * DH * DS;
        int p = tid >> 2, m0 = (tid & 3) * 32;
        __half* pdst = smy + 17408 + p * 136;
#pragma unroll
        for (int n = 0; n < 32; n += 4) {
            float4 v = *(const float4*)&Pv[p * DS + m0 + n];
            __half2* d = (__half2*)&pdst[m0 + n];
            d[0] = __floats2half2_rn(v.x, v.y);
            d[1] = __floats2half2_rn(v.z, v.w);
        }
    }
    __syncthreads();

    // ---- phase 2: Y_inter ----
#pragma unroll
    for (int nt = 0; nt < 128; nt += 16) {
        uint32_t a[4];
        {
            int arow = wid * 16 + (lane & 15);
            int acol = nt + (lane >> 4) * 8;
            LDMX4(a[0], a[1], a[2], a[3], ec + (arow * 136 + acol) * 2);
        }
#pragma unroll
        for (int nb = 0; nb < 4; nb++) {
            int brow = nb * 16 + (lane & 7) + ((lane >> 4) & 1) * 8;
            int bcol = nt + ((lane >> 3) & 1) * 8;
            uint32_t t0, t1, t2, t3;
            LDMX4(t0, t1, t2, t3, pb + (brow * 136 + bcol) * 2);
            uint32_t b0[2] = {t0, t1}, b1[2] = {t2, t3};
            MMA16816(acc[nb * 2], a, b0);
            MMA16816(acc[nb * 2 + 1], a, b1);
        }
    }

    // ---- epilogue ----
    float Dh = Dparam[h];
    {
        int r = wid * 16 + (lane >> 2);
#pragma unroll
        for (int nj = 0; nj < 8; nj++) {
            int cc = nj * 8 + (lane & 3) * 2;
            {
                int row = rowbase + r;
                float2 xv = *(const float2*)&g_xc[(long)row * CONVD + XOFF + h * DH + cc];
                *(float2*)&g_y[(long)row * DSSM + h * DH + cc] =
                    make_float2(acc[nj][0] + Dh * xv.x, acc[nj][1] + Dh * xv.y);
            }
            {
                int row = rowbase + r + 8;
                float2 xv = *(const float2*)&g_xc[(long)row * CONVD + XOFF + h * DH + cc];
                *(float2*)&g_y[(long)row * DSSM + h * DH + cc] =
                    make_float2(acc[nj][2] + Dh * xv.x, acc[nj][3] + Dh * xv.y);
            }
        }
    }
}

// ---------------- gate + RMSNorm, emits fp16 ----------------
__global__ __launch_bounds__(256)
void gatenorm_kernel(const float* __restrict__ norm_w)
{
    int row = blockIdx.x;
    int tid = threadIdx.x;
    float v[8];
    float ss = 0.f;
#pragma unroll
    for (int j = 0; j < 8; j++) {
        int cidx = tid + j * 256;
        float y = g_y[(long)row * DSSM + cidx];
        float z = g_zx[(long)row * DIP + ZOFF + cidx];
        float g = z / (1.f + __expf(-z));
        float yg = y * g;
        v[j] = yg;
        ss += yg * yg;
    }
#pragma unroll
    for (int o = 16; o > 0; o >>= 1) ss += __shfl_xor_sync(0xffffffffu, ss, o);
    __shared__ float red[8];
    __shared__ float rinv;
    if ((tid & 31) == 0) red[tid >> 5] = ss;
    __syncthreads();
    if (tid == 0) {
        float t = 0.f;
#pragma unroll
        for (int i = 0; i < 8; i++) t += red[i];
        rinv = rsqrtf(t / (float)DSSM + 1e-5f);
    }
    __syncthreads();
    float r = rinv;
#pragma unroll
    for (int j = 0; j < 8; j++) {
        int cidx = tid + j * 256;
        float val = v[j] * r * norm_w[cidx];
        g_yhi[(long)row * DSSM + cidx] = __float2half(val);
    }
}

// ---------------- host launcher ----------------
extern "C" void kernel_launch(void* const* d_in, const int* in_sizes, int n_in,
                              void* d_out, int out_size)
{
    const float* u       = (const float*)d_in[0];
    const float* W_in    = (const float*)d_in[1];
    const float* conv_w  = (const float*)d_in[2];
    const float* conv_b  = (const float*)d_in[3];
    const float* dt_bias = (const float*)d_in[4];
    const float* A_log   = (const float*)d_in[5];
    const float* Dp      = (const float*)d_in[6];
    const float* norm_w  = (const float*)d_in[7];
    const float* W_out   = (const float*)d_in[8];
    float* out = (float*)d_out;

    float *p_zx;
    cudaGetSymbolAddress((void**)&p_zx, g_zx);
    __half *p_uhi, *p_w1hi, *p_yhi, *p_w2hi;
    cudaGetSymbolAddress((void**)&p_uhi, g_uhi);
    cudaGetSymbolAddress((void**)&p_w1hi, g_w1hi);
    cudaGetSymbolAddress((void**)&p_yhi, g_yhi);
    cudaGetSymbolAddress((void**)&p_w2hi, g_w2hi);

    static int smem_set = 0;
    if (!smem_set) {
        cudaFuncSetAttribute(gemm_f16, cudaFuncAttributeMaxDynamicSharedMemorySize, 2 * STAGE_ELEMS * 2);
        cudaFuncSetAttribute(cb_mma, cudaFuncAttributeMaxDynamicSharedMemorySize, 69632);
        cudaFuncSetAttribute(states_mma, cudaFuncAttributeMaxDynamicSharedMemorySize, 53248);
        cudaFuncSetAttribute(y_mma, cudaFuncAttributeMaxDynamicSharedMemorySize, 52224);
        smem_set = 1;
    }

    // 0) conversions: u, W_in (padded), W_out -> fp16
    {
        long nq = (long)ROWS * DM / 4;
        cvt_hi_pad<<<(nq + 255) / 256, 256>>>(u, p_uhi, nq, nq);
    }
    {
        long nq = (long)DIPPAD * DM / 4, ns = (long)DIP * DM / 4;
        cvt_hi_pad<<<(nq + 255) / 256, 256>>>(W_in, p_w1hi, nq, ns);
    }
    {
        long nq = (long)DM * DSSM / 4;
        cvt_hi_pad<<<(nq + 255) / 256, 256>>>(W_out, p_w2hi, nq, nq);
    }

    // 1) in_proj (fp16 x fp16)
    gemm_f16<<<dim3(DIPPAD / 128, ROWS / 128), 256, 2 * STAGE_ELEMS * 2>>>(
        p_uhi, p_w1hi, p_zx, ROWS, DIP, DM, DIP);

    // 2) conv + silu
    conv_silu_kernel<<<dim3(CONVD / 256, ROWS / 32), 256>>>(conv_w, conv_b);

    // 3) dt / cumsum
    dtcum_kernel<<<BATCH * NC, 256>>>(dt_bias, A_log);

    // 4) CB
    cb_mma<<<BATCH * NC, 256, 69632>>>();

    // 5) states
    states_mma<<<BATCH * NC * NH, 256, 53248>>>();

    // 6) scan
    scan_kernel<<<BATCH * NH * 8, 256>>>();

    // 7) Y
    y_mma<<<BATCH * NC * NH, 256, 52224>>>(Dp);

    // 8) gate + RMSNorm
    gatenorm_kernel<<<ROWS, 256>>>(norm_w);

    // 9) out_proj (fp16 x fp16)
    gemm_f16<<<dim3(DM / 128, ROWS / 128), 256, 2 * STAGE_ELEMS * 2>>>(
        p_yhi, p_w2hi, out, ROWS, DM, DSSM, DM);

    (void)in_sizes; (void)n_in; (void)out_size;
}